// round 4
// baseline (speedup 1.0000x reference)
#include <cuda_runtime.h>
#include <cuda_bf16.h>
#include <cstdint>

// ---------------------------------------------------------------------------
// CoMA forward: 3x (ChebConv K=6 -> ReLU -> Pool) -> Linear(25024,128) -> ReLU
//               -> Linear(128,2)
// Node-major layout (N, B*F). Chebyshev propagation done GATHER-style via a
// per-call fixed-stride CSR bucket build. Gather kernel uses CH float4 chunks
// per thread + 2-edge batches for high memory-level parallelism.
// ---------------------------------------------------------------------------

#define BATCH 32
#define KORD 6
#define CAP 64   // max in-degree bucket capacity (Poisson(6): P(>=64) ~ 0)

static const int N0 = 50000, N1 = 12500, N2 = 3125, N3 = 782;
static const int E0 = 300000, E1 = 75000, E2 = 18750;

// scratch pool: 7 slots of 6.4M floats + enc accumulator
#define SLOT 6400000
__device__ __align__(16) float g_buf[7 * SLOT + 4096];
// CSR buckets (sized for layer 0): packed (col, norm-bits) pairs
__device__ __align__(16) int2 g_bpair[(size_t)50000 * CAP];
__device__ int g_deg[50000];

// ---------------------------------------------------------------------------
// transpose x (B, N, 3) -> xt (N, B*3)
__global__ void k_transpose(const float* __restrict__ x, float* __restrict__ xt, int N)
{
    int idx = blockIdx.x * blockDim.x + threadIdx.x;
    int total = BATCH * N * 3;
    if (idx >= total) return;
    int c = idx % 3;
    int n = (idx / 3) % N;
    int b = idx / (3 * N);
    xt[(size_t)n * (BATCH * 3) + b * 3 + c] = x[idx];
}

__global__ void k_zero4(float4* p, int n4)
{
    int i = blockIdx.x * blockDim.x + threadIdx.x;
    if (i < n4) p[i] = make_float4(0.f, 0.f, 0.f, 0.f);
}

__global__ void k_zero_deg(int n)
{
    int i = blockIdx.x * blockDim.x + threadIdx.x;
    if (i < n) g_deg[i] = 0;
}

// build fixed-stride incoming-edge buckets
__global__ void k_bucket(const int* __restrict__ rows, const int* __restrict__ cols,
                         const float* __restrict__ norm, int E)
{
    int e = blockIdx.x * blockDim.x + threadIdx.x;
    if (e >= E) return;
    int r = rows[e];
    int d = atomicAdd(&g_deg[r], 1);
    if (d < CAP) {
        g_bpair[(size_t)r * CAP + d] = make_int2(cols[e], __float_as_int(norm[e]));
    }
}

// ---------------------------------------------------------------------------
// gather propagate:
//   dst[n] = (prev ? -prev[n] : 0) + scale * sum_{j in bucket(n)} norm_j * src[col_j]
// LPN lanes per node, CH float4 chunks per lane (chunk c4 + t*LPN).
template <int W4, int LPN, int CH>
__global__ void k_prop_g(const float* __restrict__ prev,
                         const float* __restrict__ src,
                         float* __restrict__ dst,
                         float scale, int N)
{
    static_assert(LPN * CH == W4, "bad chunking");
    int tid  = threadIdx.x;
    int node = blockIdx.x * (256 / LPN) + tid / LPN;
    int c4   = tid % LPN;
    if (node >= N) return;

    int d = min(g_deg[node], CAP);
    const int2* bp = g_bpair + (size_t)node * CAP;
    const float4* s4 = (const float4*)src;

    float4 acc[CH];
    if (prev) {
        const float4* p4 = (const float4*)prev + (size_t)node * W4 + c4;
#pragma unroll
        for (int t = 0; t < CH; t++) {
            float4 p = p4[t * LPN];
            acc[t] = make_float4(-p.x, -p.y, -p.z, -p.w);
        }
    } else {
#pragma unroll
        for (int t = 0; t < CH; t++) acc[t] = make_float4(0.f, 0.f, 0.f, 0.f);
    }

    int j = 0;
    for (; j + 2 <= d; j += 2) {
        int2 p0 = bp[j];
        int2 p1 = bp[j + 1];
        const float4* sa = s4 + (size_t)p0.x * W4 + c4;
        const float4* sb = s4 + (size_t)p1.x * W4 + c4;
        float4 va[CH], vb[CH];
#pragma unroll
        for (int t = 0; t < CH; t++) va[t] = sa[t * LPN];
#pragma unroll
        for (int t = 0; t < CH; t++) vb[t] = sb[t * LPN];
        float n0 = __int_as_float(p0.y) * scale;
        float n1 = __int_as_float(p1.y) * scale;
#pragma unroll
        for (int t = 0; t < CH; t++) {
            acc[t].x += n0 * va[t].x + n1 * vb[t].x;
            acc[t].y += n0 * va[t].y + n1 * vb[t].y;
            acc[t].z += n0 * va[t].z + n1 * vb[t].z;
            acc[t].w += n0 * va[t].w + n1 * vb[t].w;
        }
    }
    if (j < d) {
        int2 p0 = bp[j];
        const float4* sa = s4 + (size_t)p0.x * W4 + c4;
        float n0 = __int_as_float(p0.y) * scale;
#pragma unroll
        for (int t = 0; t < CH; t++) {
            float4 a = sa[t * LPN];
            acc[t].x += n0 * a.x; acc[t].y += n0 * a.y;
            acc[t].z += n0 * a.z; acc[t].w += n0 * a.w;
        }
    }

    float4* d4 = (float4*)dst + (size_t)node * W4 + c4;
#pragma unroll
    for (int t = 0; t < CH; t++) d4[t * LPN] = acc[t];
}

// ---------------------------------------------------------------------------
// fused: for each pooled output row r:
//   out[r] = sum_{j=0..2} pval * relu( bias + sum_k T_k[col_j] @ w_k )
struct TPtrs { const float* T[KORD]; };

template <int FIN, int FOUT>
__global__ void k_pool_cheb(TPtrs tp, const float* __restrict__ w,
                            const float* __restrict__ bias,
                            const int* __restrict__ pcols,
                            const float* __restrict__ pvals,
                            float* __restrict__ out, int n_out)
{
    constexpr int FINP = (FIN % 2 == 0) ? FIN + 1 : FIN;   // bank-conflict pad
    constexpr int NO   = FOUT / 4;                          // outputs per thread

    __shared__ __align__(16) float sW[KORD * FIN * FOUT];
    __shared__ float sT[KORD][32 * FINP];

    int tid = threadIdx.x;
    for (int i = tid; i < KORD * FIN * FOUT; i += 128) sW[i] = w[i];

    int b  = tid & 31;
    int og = tid >> 5;      // 0..3

    float bz[NO], acc[NO];
#pragma unroll
    for (int j = 0; j < NO; j++) { bz[j] = bias[og * NO + j]; acc[j] = 0.f; }

    int r = blockIdx.x;
    if (r >= n_out) return;

#pragma unroll
    for (int j3 = 0; j3 < 3; j3++) {
        int   col = pcols[r * 3 + j3];
        float pv  = pvals[r * 3 + j3];
        __syncthreads();
#pragma unroll
        for (int k = 0; k < KORD; k++) {
            const float* src = tp.T[k] + (size_t)col * (32 * FIN);
            for (int i = tid; i < 32 * FIN; i += 128) {
                int bb = i / FIN, ii = i - bb * FIN;
                sT[k][bb * FINP + ii] = src[i];
            }
        }
        __syncthreads();

        float y[NO];
#pragma unroll
        for (int j = 0; j < NO; j++) y[j] = bz[j];

#pragma unroll
        for (int k = 0; k < KORD; k++) {
            float rT[FIN];
#pragma unroll
            for (int i = 0; i < FIN; i++) rT[i] = sT[k][b * FINP + i];
#pragma unroll
            for (int i = 0; i < FIN; i++) {
                const float* wrow = &sW[(k * FIN + i) * FOUT + og * NO];
#pragma unroll
                for (int j = 0; j < NO; j += 4) {
                    float4 w4 = *(const float4*)(wrow + j);
                    y[j + 0] += rT[i] * w4.x;
                    y[j + 1] += rT[i] * w4.y;
                    y[j + 2] += rT[i] * w4.z;
                    y[j + 3] += rT[i] * w4.w;
                }
            }
        }
#pragma unroll
        for (int j = 0; j < NO; j++) acc[j] += pv * fmaxf(y[j], 0.f);
    }

    float* o = out + ((size_t)r * 32 + b) * FOUT + og * NO;
#pragma unroll
    for (int j = 0; j < NO; j++) o[j] = acc[j];
}

// ---------------------------------------------------------------------------
// encoder split-K GEMM: enc[b,z] += sum_{n,f} h[n,b,f] * wenc[(n*32+f)*128+z]
__global__ void k_enc(const float* __restrict__ h, const float* __restrict__ wenc,
                      float* __restrict__ enc, int N)
{
    __shared__ float sH[8 * 32 * 32];
    int tid = threadIdx.x;
    int n0  = blockIdx.x * 8;
    int nn  = min(8, N - n0);
    for (int i = tid; i < nn * 1024; i += 256) sH[i] = h[(size_t)n0 * 1024 + i];
    __syncthreads();

    int z  = tid & 127;
    int bh = tid >> 7;   // 0..1
    float acc[16];
#pragma unroll
    for (int j = 0; j < 16; j++) acc[j] = 0.f;

    for (int n = 0; n < nn; n++) {
#pragma unroll
        for (int f = 0; f < 32; f++) {
            float wv = wenc[((size_t)(n0 + n) * 32 + f) * 128 + z];
#pragma unroll
            for (int j = 0; j < 16; j++)
                acc[j] += wv * sH[n * 1024 + (bh * 16 + j) * 32 + f];
        }
    }
#pragma unroll
    for (int j = 0; j < 16; j++)
        atomicAdd(&enc[(bh * 16 + j) * 128 + z], acc[j]);
}

__global__ void k_final(const float* __restrict__ enc, const float* __restrict__ benc,
                        const float* __restrict__ wcls, const float* __restrict__ bcls,
                        float* __restrict__ out)
{
    int t = threadIdx.x;
    if (t >= 64) return;
    int b = t >> 1, c = t & 1;
    float a = bcls[c];
    for (int z = 0; z < 128; z++) {
        float e = fmaxf(enc[b * 128 + z] + benc[z], 0.f);
        a += e * wcls[z * 2 + c];
    }
    out[b * 2 + c] = a;
}

// ---------------------------------------------------------------------------
template <int FIN, int LPN, int CH>
static void run_cheb_g(float* Ts[6], int N, int E,
                       const int* edge, const float* norm)
{
    constexpr int W4  = (32 * FIN) / 4;
    static_assert(LPN * CH == W4, "bad chunking");
    constexpr int NPB = 256 / LPN;       // nodes per block
    int gN = (N + NPB - 1) / NPB;

    // build buckets
    k_zero_deg<<<(N + 255) / 256, 256>>>(N);
    k_bucket<<<(E + 255) / 256, 256>>>(edge, edge + E, norm, E);

    // T1 = L @ T0
    k_prop_g<W4, LPN, CH><<<gN, 256>>>(nullptr, Ts[0], Ts[1], 1.f, N);
    // Tk = 2 L T_{k-1} - T_{k-2}
    for (int k = 2; k < KORD; k++)
        k_prop_g<W4, LPN, CH><<<gN, 256>>>(Ts[k - 2], Ts[k - 1], Ts[k], 2.f, N);
}

extern "C" void kernel_launch(void* const* d_in, const int* in_sizes, int n_in,
                              void* d_out, int out_size)
{
    const float* x;
    const int*   edge[3];
    const float* norm[3];
    const int*   pidx[3];
    const float* pval[3];
    const float *w[3], *bb[3], *wenc, *benc, *wcls, *bcls;

    if (in_sizes[3] == 150000) {
        // reference-signature order
        x = (const float*)d_in[0];
        edge[0] = (const int*)d_in[1];  norm[0] = (const float*)d_in[2];
        edge[1] = (const int*)d_in[3];  norm[1] = (const float*)d_in[4];
        edge[2] = (const int*)d_in[5];  norm[2] = (const float*)d_in[6];
        pidx[0] = (const int*)d_in[7];  pval[0] = (const float*)d_in[8];
        pidx[1] = (const int*)d_in[9];  pval[1] = (const float*)d_in[10];
        pidx[2] = (const int*)d_in[11]; pval[2] = (const float*)d_in[12];
    } else {
        // setup_inputs dict order
        x = (const float*)d_in[0];
        edge[0] = (const int*)d_in[1];  norm[0] = (const float*)d_in[2];
        pidx[0] = (const int*)d_in[3];  pval[0] = (const float*)d_in[4];
        edge[1] = (const int*)d_in[5];  norm[1] = (const float*)d_in[6];
        pidx[1] = (const int*)d_in[7];  pval[1] = (const float*)d_in[8];
        edge[2] = (const int*)d_in[9];  norm[2] = (const float*)d_in[10];
        pidx[2] = (const int*)d_in[11]; pval[2] = (const float*)d_in[12];
    }
    w[0]  = (const float*)d_in[13]; bb[0] = (const float*)d_in[14];
    w[1]  = (const float*)d_in[15]; bb[1] = (const float*)d_in[16];
    w[2]  = (const float*)d_in[17]; bb[2] = (const float*)d_in[18];
    wenc  = (const float*)d_in[19]; benc  = (const float*)d_in[20];
    wcls  = (const float*)d_in[21]; bcls  = (const float*)d_in[22];

    float* base = nullptr;
    cudaGetSymbolAddress((void**)&base, g_buf);
    float* H0 = base;
    float* H1 = base + (size_t)SLOT;
    float* T1 = base + (size_t)2 * SLOT;
    float* T2 = base + (size_t)3 * SLOT;
    float* T3 = base + (size_t)4 * SLOT;
    float* T4 = base + (size_t)5 * SLOT;
    float* T5 = base + (size_t)6 * SLOT;
    float* enc = base + (size_t)7 * SLOT;

    // ---- layer 0: N0, Fin=3, Fout=16 ----
    {
        int total = BATCH * N0 * 3;
        k_transpose<<<(total + 255) / 256, 256>>>(x, H0, N0);
        float* Ts[6] = {H0, T1, T2, T3, T4, T5};
        run_cheb_g<3, 8, 3>(Ts, N0, E0, edge[0], norm[0]);
        TPtrs tp; tp.T[0] = H0; tp.T[1] = T1; tp.T[2] = T2; tp.T[3] = T3; tp.T[4] = T4; tp.T[5] = T5;
        k_pool_cheb<3, 16><<<N1, 128>>>(tp, w[0], bb[0],
                                        pidx[0] + (size_t)N1 * 3, pval[0], H1, N1);
    }
    // ---- layer 1: N1, Fin=16, Fout=16 ----
    {
        float* Ts[6] = {H1, T1, T2, T3, T4, T5};
        run_cheb_g<16, 32, 4>(Ts, N1, E1, edge[1], norm[1]);
        TPtrs tp; tp.T[0] = H1; tp.T[1] = T1; tp.T[2] = T2; tp.T[3] = T3; tp.T[4] = T4; tp.T[5] = T5;
        k_pool_cheb<16, 16><<<N2, 128>>>(tp, w[1], bb[1],
                                         pidx[1] + (size_t)N2 * 3, pval[1], H0, N2);
    }
    // ---- layer 2: N2, Fin=16, Fout=32 ----
    {
        float* Ts[6] = {H0, T1, T2, T3, T4, T5};
        run_cheb_g<16, 32, 4>(Ts, N2, E2, edge[2], norm[2]);
        TPtrs tp; tp.T[0] = H0; tp.T[1] = T1; tp.T[2] = T2; tp.T[3] = T3; tp.T[4] = T4; tp.T[5] = T5;
        k_pool_cheb<16, 32><<<N3, 128>>>(tp, w[2], bb[2],
                                         pidx[2] + (size_t)N3 * 3, pval[2], H1, N3);
    }
    // ---- encoder + classifier ----
    k_zero4<<<4, 256>>>((float4*)enc, 1024);
    k_enc<<<(N3 + 7) / 8, 256>>>(H1, wenc, enc, N3);
    k_final<<<1, 64>>>(enc, benc, wcls, bcls, (float*)d_out);
}

// round 6
// speedup vs baseline: 1.0115x; 1.0115x over previous
#include <cuda_runtime.h>
#include <cuda_bf16.h>
#include <cstdint>

// ---------------------------------------------------------------------------
// CoMA forward: 3x (ChebConv K=6 -> ReLU -> Pool) -> Linear(25024,128) -> ReLU
//               -> Linear(128,2)
// Node-major layout (N, B*F). Chebyshev propagation GATHER-style via padded
// fixed-stride CSR buckets (built once for all layers). Gather kernel uses
// CH float4 chunks/thread, 2-edge batches, metadata double-buffering.
// ---------------------------------------------------------------------------

#define BATCH 32
#define KORD 6
#define CAP 32   // max in-degree bucket capacity (Poisson(6): P(>=32) ~ 1e-15)

#define N0 50000
#define N1 12500
#define N2 3125
#define N3 782
#define E0 300000
#define E1 75000
#define E2 18750

#define DEG_OFF0 0
#define DEG_OFF1 N0
#define DEG_OFF2 (N0 + N1)
#define NDEG (N0 + N1 + N2)

#define B_OFF0 ((size_t)0)
#define B_OFF1 ((size_t)N0 * CAP)
#define B_OFF2 ((size_t)(N0 + N1) * CAP)

// scratch pool: 7 slots of 6.4M floats + enc accumulator
#define SLOT 6400000
__device__ __align__(16) float g_buf[7 * SLOT + 4096];
__device__ __align__(16) int2 g_bpair[(size_t)NDEG * CAP + 8];
__device__ int g_deg[NDEG];

// ---------------------------------------------------------------------------
// init: zero all deg counters + enc accumulator
__global__ void k_init(float4* enc4)
{
    int i = blockIdx.x * blockDim.x + threadIdx.x;
    if (i < NDEG) g_deg[i] = 0;
    if (i < 1024) enc4[i] = make_float4(0.f, 0.f, 0.f, 0.f);
}

// build fixed-stride incoming-edge buckets for ALL layers in one launch
__global__ void k_bucket_all(const int* __restrict__ e0, const float* __restrict__ nm0,
                             const int* __restrict__ e1, const float* __restrict__ nm1,
                             const int* __restrict__ e2, const float* __restrict__ nm2)
{
    int e = blockIdx.x * blockDim.x + threadIdx.x;
    const int* rows; const float* nm; int idx, E; int doff; size_t boff;
    if (e < E0)            { idx = e;             rows = e0; nm = nm0; E = E0; doff = DEG_OFF0; boff = B_OFF0; }
    else if (e < E0 + E1)  { idx = e - E0;        rows = e1; nm = nm1; E = E1; doff = DEG_OFF1; boff = B_OFF1; }
    else if (e < E0+E1+E2) { idx = e - E0 - E1;   rows = e2; nm = nm2; E = E2; doff = DEG_OFF2; boff = B_OFF2; }
    else return;
    int r = rows[idx];
    int c = rows[idx + E];          // cols stored after rows
    int d = atomicAdd(&g_deg[doff + r], 1);
    if (d < CAP)
        g_bpair[boff + (size_t)r * CAP + d] = make_int2(c, __float_as_int(nm[idx]));
}

// pad each bucket row to even length with (col=0, val=0)
__global__ void k_pad()
{
    int n = blockIdx.x * blockDim.x + threadIdx.x;
    if (n < N0) {
        int d = min(g_deg[DEG_OFF0 + n], CAP);
        if (d & 1) g_bpair[B_OFF0 + (size_t)n * CAP + d] = make_int2(0, 0);
    }
    if (n < N1) {
        int d = min(g_deg[DEG_OFF1 + n], CAP);
        if (d & 1) g_bpair[B_OFF1 + (size_t)n * CAP + d] = make_int2(0, 0);
    }
    if (n < N2) {
        int d = min(g_deg[DEG_OFF2 + n], CAP);
        if (d & 1) g_bpair[B_OFF2 + (size_t)n * CAP + d] = make_int2(0, 0);
    }
}

// ---------------------------------------------------------------------------
// transpose x (B, N, 3) -> xt (N, B*3)
__global__ void k_transpose(const float* __restrict__ x, float* __restrict__ xt, int N)
{
    int idx = blockIdx.x * blockDim.x + threadIdx.x;
    int total = BATCH * N * 3;
    if (idx >= total) return;
    int c = idx % 3;
    int n = (idx / 3) % N;
    int b = idx / (3 * N);
    xt[(size_t)n * (BATCH * 3) + b * 3 + c] = x[idx];
}

// ---------------------------------------------------------------------------
// gather propagate:
//   dst[n] = (HASPREV ? -prev[n] : 0) + SCALEI * sum_j norm_j * src[col_j]
// LPN lanes per node, CH float4 chunks per lane; padded even-degree loop with
// metadata double-buffering.
template <int W4, int LPN, int CH, int SCALEI, bool HASPREV>
__global__ void __launch_bounds__(256, (LPN == 8) ? 6 : 5)
k_prop_g(const float* __restrict__ prev, const float* __restrict__ src,
         float* __restrict__ dst, int N,
         const int2* __restrict__ bp_base, const int* __restrict__ deg)
{
    static_assert(LPN * CH == W4, "bad chunking");
    int tid  = threadIdx.x;
    int node = blockIdx.x * (256 / LPN) + tid / LPN;
    int c4   = tid % LPN;
    if (node >= N) return;

    int d    = min(deg[node], CAP);
    int dpad = (d + 1) & ~1;
    const int2*   bp = bp_base + (size_t)node * CAP;
    const float4* s4 = (const float4*)src;

    float4 acc[CH];
    if (HASPREV) {
        const float4* p4 = (const float4*)prev + (size_t)node * W4 + c4;
#pragma unroll
        for (int t = 0; t < CH; t++) {
            float4 p = p4[t * LPN];
            acc[t] = make_float4(-p.x, -p.y, -p.z, -p.w);
        }
    } else {
#pragma unroll
        for (int t = 0; t < CH; t++) acc[t] = make_float4(0.f, 0.f, 0.f, 0.f);
    }

    int2 m0 = bp[0], m1 = bp[1];          // safe: row has CAP entries
    for (int j = 0; j < dpad; j += 2) {
        int2 n0 = bp[j + 2];               // prefetch next pair (array has slack)
        int2 n1 = bp[j + 3];
        const float4* sa = s4 + (size_t)m0.x * W4 + c4;
        const float4* sb = s4 + (size_t)m1.x * W4 + c4;
        float4 va[CH], vb[CH];
#pragma unroll
        for (int t = 0; t < CH; t++) va[t] = sa[t * LPN];
#pragma unroll
        for (int t = 0; t < CH; t++) vb[t] = sb[t * LPN];
        float f0 = __int_as_float(m0.y) * (float)SCALEI;
        float f1 = __int_as_float(m1.y) * (float)SCALEI;
#pragma unroll
        for (int t = 0; t < CH; t++) {
            acc[t].x += f0 * va[t].x + f1 * vb[t].x;
            acc[t].y += f0 * va[t].y + f1 * vb[t].y;
            acc[t].z += f0 * va[t].z + f1 * vb[t].z;
            acc[t].w += f0 * va[t].w + f1 * vb[t].w;
        }
        m0 = n0; m1 = n1;
    }

    float4* d4 = (float4*)dst + (size_t)node * W4 + c4;
#pragma unroll
    for (int t = 0; t < CH; t++) d4[t * LPN] = acc[t];
}

// ---------------------------------------------------------------------------
// fused: for each pooled output row r:
//   out[r] = sum_{j=0..2} pval * relu( bias + sum_k T_k[col_j] @ w_k )
struct TPtrs { const float* T[KORD]; };

template <int FIN, int FOUT>
__global__ void k_pool_cheb(TPtrs tp, const float* __restrict__ w,
                            const float* __restrict__ bias,
                            const int* __restrict__ pcols,
                            const float* __restrict__ pvals,
                            float* __restrict__ out, int n_out)
{
    constexpr int FINP = (FIN % 2 == 0) ? FIN + 1 : FIN;   // bank-conflict pad
    constexpr int NO   = FOUT / 4;                          // outputs per thread

    __shared__ __align__(16) float sW[KORD * FIN * FOUT];
    __shared__ float sT[KORD][32 * FINP];

    int tid = threadIdx.x;
    for (int i = tid; i < KORD * FIN * FOUT; i += 128) sW[i] = w[i];

    int b  = tid & 31;
    int og = tid >> 5;      // 0..3

    float bz[NO], acc[NO];
#pragma unroll
    for (int j = 0; j < NO; j++) { bz[j] = bias[og * NO + j]; acc[j] = 0.f; }

    int r = blockIdx.x;
    if (r >= n_out) return;

#pragma unroll
    for (int j3 = 0; j3 < 3; j3++) {
        int   col = pcols[r * 3 + j3];
        float pv  = pvals[r * 3 + j3];
        __syncthreads();
#pragma unroll
        for (int k = 0; k < KORD; k++) {
            const float* src = tp.T[k] + (size_t)col * (32 * FIN);
            for (int i = tid; i < 32 * FIN; i += 128) {
                int bb = i / FIN, ii = i - bb * FIN;
                sT[k][bb * FINP + ii] = src[i];
            }
        }
        __syncthreads();

        float y[NO];
#pragma unroll
        for (int j = 0; j < NO; j++) y[j] = bz[j];

#pragma unroll
        for (int k = 0; k < KORD; k++) {
            float rT[FIN];
#pragma unroll
            for (int i = 0; i < FIN; i++) rT[i] = sT[k][b * FINP + i];
#pragma unroll
            for (int i = 0; i < FIN; i++) {
                const float* wrow = &sW[(k * FIN + i) * FOUT + og * NO];
#pragma unroll
                for (int j = 0; j < NO; j += 4) {
                    float4 w4 = *(const float4*)(wrow + j);
                    y[j + 0] += rT[i] * w4.x;
                    y[j + 1] += rT[i] * w4.y;
                    y[j + 2] += rT[i] * w4.z;
                    y[j + 3] += rT[i] * w4.w;
                }
            }
        }
#pragma unroll
        for (int j = 0; j < NO; j++) acc[j] += pv * fmaxf(y[j], 0.f);
    }

    float* o = out + ((size_t)r * 32 + b) * FOUT + og * NO;
#pragma unroll
    for (int j = 0; j < NO; j++) o[j] = acc[j];
}

// ---------------------------------------------------------------------------
// encoder split-K GEMM: enc[b,z] += sum_{n,f} h[n,b,f] * wenc[(n*32+f)*128+z]
__global__ void k_enc(const float* __restrict__ h, const float* __restrict__ wenc,
                      float* __restrict__ enc, int N)
{
    __shared__ float sH[8 * 32 * 32];
    int tid = threadIdx.x;
    int n0  = blockIdx.x * 8;
    int nn  = min(8, N - n0);
    for (int i = tid; i < nn * 1024; i += 256) sH[i] = h[(size_t)n0 * 1024 + i];
    __syncthreads();

    int z  = tid & 127;
    int bh = tid >> 7;   // 0..1
    float acc[16];
#pragma unroll
    for (int j = 0; j < 16; j++) acc[j] = 0.f;

    for (int n = 0; n < nn; n++) {
#pragma unroll
        for (int f = 0; f < 32; f++) {
            float wv = wenc[((size_t)(n0 + n) * 32 + f) * 128 + z];
#pragma unroll
            for (int j = 0; j < 16; j++)
                acc[j] += wv * sH[n * 1024 + (bh * 16 + j) * 32 + f];
        }
    }
#pragma unroll
    for (int j = 0; j < 16; j++)
        atomicAdd(&enc[(bh * 16 + j) * 128 + z], acc[j]);
}

__global__ void k_final(const float* __restrict__ enc, const float* __restrict__ benc,
                        const float* __restrict__ wcls, const float* __restrict__ bcls,
                        float* __restrict__ out)
{
    int t = threadIdx.x;
    if (t >= 64) return;
    int b = t >> 1, c = t & 1;
    float a = bcls[c];
    for (int z = 0; z < 128; z++) {
        float e = fmaxf(enc[b * 128 + z] + benc[z], 0.f);
        a += e * wcls[z * 2 + c];
    }
    out[b * 2 + c] = a;
}

// ---------------------------------------------------------------------------
template <int FIN, int LPN, int CH>
static void run_cheb_g(float* Ts[6], int N, const int2* bp, const int* deg)
{
    constexpr int W4  = (32 * FIN) / 4;
    constexpr int NPB = 256 / LPN;       // nodes per block
    int gN = (N + NPB - 1) / NPB;

    // T1 = L @ T0
    k_prop_g<W4, LPN, CH, 1, false><<<gN, 256>>>(nullptr, Ts[0], Ts[1], N, bp, deg);
    // Tk = 2 L T_{k-1} - T_{k-2}
    for (int k = 2; k < KORD; k++)
        k_prop_g<W4, LPN, CH, 2, true><<<gN, 256>>>(Ts[k - 2], Ts[k - 1], Ts[k], N, bp, deg);
}

extern "C" void kernel_launch(void* const* d_in, const int* in_sizes, int n_in,
                              void* d_out, int out_size)
{
    const float* x;
    const int*   edge[3];
    const float* norm[3];
    const int*   pidx[3];
    const float* pval[3];
    const float *w[3], *bb[3], *wenc, *benc, *wcls, *bcls;

    if (in_sizes[3] == 150000) {
        // reference-signature order
        x = (const float*)d_in[0];
        edge[0] = (const int*)d_in[1];  norm[0] = (const float*)d_in[2];
        edge[1] = (const int*)d_in[3];  norm[1] = (const float*)d_in[4];
        edge[2] = (const int*)d_in[5];  norm[2] = (const float*)d_in[6];
        pidx[0] = (const int*)d_in[7];  pval[0] = (const float*)d_in[8];
        pidx[1] = (const int*)d_in[9];  pval[1] = (const float*)d_in[10];
        pidx[2] = (const int*)d_in[11]; pval[2] = (const float*)d_in[12];
    } else {
        // setup_inputs dict order
        x = (const float*)d_in[0];
        edge[0] = (const int*)d_in[1];  norm[0] = (const float*)d_in[2];
        pidx[0] = (const int*)d_in[3];  pval[0] = (const float*)d_in[4];
        edge[1] = (const int*)d_in[5];  norm[1] = (const float*)d_in[6];
        pidx[1] = (const int*)d_in[7];  pval[1] = (const float*)d_in[8];
        edge[2] = (const int*)d_in[9];  norm[2] = (const float*)d_in[10];
        pidx[2] = (const int*)d_in[11]; pval[2] = (const float*)d_in[12];
    }
    w[0]  = (const float*)d_in[13]; bb[0] = (const float*)d_in[14];
    w[1]  = (const float*)d_in[15]; bb[1] = (const float*)d_in[16];
    w[2]  = (const float*)d_in[17]; bb[2] = (const float*)d_in[18];
    wenc  = (const float*)d_in[19]; benc  = (const float*)d_in[20];
    wcls  = (const float*)d_in[21]; bcls  = (const float*)d_in[22];

    float* base = nullptr;
    cudaGetSymbolAddress((void**)&base, g_buf);
    int2* bpair = nullptr;
    cudaGetSymbolAddress((void**)&bpair, g_bpair);
    int* deg = nullptr;
    cudaGetSymbolAddress((void**)&deg, g_deg);

    float* H0 = base;
    float* H1 = base + (size_t)SLOT;
    float* T1 = base + (size_t)2 * SLOT;
    float* T2 = base + (size_t)3 * SLOT;
    float* T3 = base + (size_t)4 * SLOT;
    float* T4 = base + (size_t)5 * SLOT;
    float* T5 = base + (size_t)6 * SLOT;
    float* enc = base + (size_t)7 * SLOT;

    // ---- setup: buckets for all layers, enc zero, transpose ----
    k_init<<<(NDEG + 255) / 256, 256>>>((float4*)enc);
    k_bucket_all<<<(E0 + E1 + E2 + 255) / 256, 256>>>(edge[0], norm[0],
                                                      edge[1], norm[1],
                                                      edge[2], norm[2]);
    k_pad<<<(N0 + 255) / 256, 256>>>();
    k_transpose<<<(BATCH * N0 * 3 + 255) / 256, 256>>>(x, H0, N0);

    // ---- layer 0: N0, Fin=3, Fout=16 ----
    {
        float* Ts[6] = {H0, T1, T2, T3, T4, T5};
        run_cheb_g<3, 8, 3>(Ts, N0, bpair + B_OFF0, deg + DEG_OFF0);
        TPtrs tp; tp.T[0] = H0; tp.T[1] = T1; tp.T[2] = T2; tp.T[3] = T3; tp.T[4] = T4; tp.T[5] = T5;
        k_pool_cheb<3, 16><<<N1, 128>>>(tp, w[0], bb[0],
                                        pidx[0] + (size_t)N1 * 3, pval[0], H1, N1);
    }
    // ---- layer 1: N1, Fin=16, Fout=16 ----
    {
        float* Ts[6] = {H1, T1, T2, T3, T4, T5};
        run_cheb_g<16, 32, 4>(Ts, N1, bpair + B_OFF1, deg + DEG_OFF1);
        TPtrs tp; tp.T[0] = H1; tp.T[1] = T1; tp.T[2] = T2; tp.T[3] = T3; tp.T[4] = T4; tp.T[5] = T5;
        k_pool_cheb<16, 16><<<N2, 128>>>(tp, w[1], bb[1],
                                         pidx[1] + (size_t)N2 * 3, pval[1], H0, N2);
    }
    // ---- layer 2: N2, Fin=16, Fout=32 ----
    {
        float* Ts[6] = {H0, T1, T2, T3, T4, T5};
        run_cheb_g<16, 32, 4>(Ts, N2, bpair + B_OFF2, deg + DEG_OFF2);
        TPtrs tp; tp.T[0] = H0; tp.T[1] = T1; tp.T[2] = T2; tp.T[3] = T3; tp.T[4] = T4; tp.T[5] = T5;
        k_pool_cheb<16, 32><<<N3, 128>>>(tp, w[2], bb[2],
                                         pidx[2] + (size_t)N3 * 3, pval[2], H1, N3);
    }
    // ---- encoder + classifier ----
    k_enc<<<(N3 + 7) / 8, 256>>>(H1, wenc, enc, N3);
    k_final<<<1, 64>>>(enc, benc, wcls, bcls, (float*)d_out);
}

// round 7
// speedup vs baseline: 1.1854x; 1.1719x over previous
#include <cuda_runtime.h>
#include <cuda_fp16.h>
#include <cstdint>

// ---------------------------------------------------------------------------
// CoMA forward: 3x (ChebConv K=6 -> ReLU -> Pool) -> Linear(25024,128) -> ReLU
//               -> Linear(128,2)
// Node-major layout (N, B*F). All node-feature buffers stored as FP16 (halves
// gather traffic); all arithmetic accumulates in FP32. Chebyshev propagation
// GATHER-style via padded fixed-stride CSR buckets built once for all layers.
// ---------------------------------------------------------------------------

#define BATCH 32
#define KORD 6
#define CAP 32   // max in-degree bucket capacity (Poisson(6): P(>=32) ~ 1e-15)

#define N0 50000
#define N1 12500
#define N2 3125
#define N3 782
#define E0 300000
#define E1 75000
#define E2 18750

#define DEG_OFF0 0
#define DEG_OFF1 N0
#define DEG_OFF2 (N0 + N1)
#define NDEG (N0 + N1 + N2)

#define B_OFF0 ((size_t)0)
#define B_OFF1 ((size_t)N0 * CAP)
#define B_OFF2 ((size_t)(N0 + N1) * CAP)

// scratch: 7 slots of 6.5M halves (13MB each)
#define SLOTH 6500000
__device__ __align__(16) __half g_h[(size_t)7 * SLOTH + 64];
__device__ float g_enc[4096];
__device__ __align__(16) int2 g_bpair[(size_t)NDEG * CAP + 8];
__device__ int g_deg[NDEG];

// ---------------------------------------------------------------------------
// init: zero all deg counters + enc accumulator
__global__ void k_init()
{
    int i = blockIdx.x * blockDim.x + threadIdx.x;
    if (i < NDEG) g_deg[i] = 0;
    if (i < 4096) g_enc[i] = 0.f;
}

// build fixed-stride incoming-edge buckets for ALL layers in one launch
__global__ void k_bucket_all(const int* __restrict__ e0, const float* __restrict__ nm0,
                             const int* __restrict__ e1, const float* __restrict__ nm1,
                             const int* __restrict__ e2, const float* __restrict__ nm2)
{
    int e = blockIdx.x * blockDim.x + threadIdx.x;
    const int* rows; const float* nm; int idx, E; int doff; size_t boff;
    if (e < E0)            { idx = e;             rows = e0; nm = nm0; E = E0; doff = DEG_OFF0; boff = B_OFF0; }
    else if (e < E0 + E1)  { idx = e - E0;        rows = e1; nm = nm1; E = E1; doff = DEG_OFF1; boff = B_OFF1; }
    else if (e < E0+E1+E2) { idx = e - E0 - E1;   rows = e2; nm = nm2; E = E2; doff = DEG_OFF2; boff = B_OFF2; }
    else return;
    int r = rows[idx];
    int c = rows[idx + E];          // cols stored after rows
    int d = atomicAdd(&g_deg[doff + r], 1);
    if (d < CAP)
        g_bpair[boff + (size_t)r * CAP + d] = make_int2(c, __float_as_int(nm[idx]));
}

// pad each bucket row to even length with (col=0, val=0)
__global__ void k_pad()
{
    int n = blockIdx.x * blockDim.x + threadIdx.x;
    if (n < N0) {
        int d = min(g_deg[DEG_OFF0 + n], CAP);
        if (d & 1) g_bpair[B_OFF0 + (size_t)n * CAP + d] = make_int2(0, 0);
    }
    if (n < N1) {
        int d = min(g_deg[DEG_OFF1 + n], CAP);
        if (d & 1) g_bpair[B_OFF1 + (size_t)n * CAP + d] = make_int2(0, 0);
    }
    if (n < N2) {
        int d = min(g_deg[DEG_OFF2 + n], CAP);
        if (d & 1) g_bpair[B_OFF2 + (size_t)n * CAP + d] = make_int2(0, 0);
    }
}

// ---------------------------------------------------------------------------
// transpose x (B, N, 3) fp32 -> xt (N, B*3) fp16, smem-tiled & coalesced
__global__ void k_transpose_h(const float* __restrict__ x, __half* __restrict__ xt, int N)
{
    __shared__ float s[32][97];
    int n0  = blockIdx.x * 32;
    int tid = threadIdx.x;
    for (int i = tid; i < 32 * 96; i += 256) {
        int b = i / 96, r = i % 96;        // r = nl*3 + c
        int nl = r / 3, c = r % 3;
        int n = n0 + nl;
        if (n < N) s[nl][b * 3 + c] = x[((size_t)b * N + n) * 3 + c];
    }
    __syncthreads();
    for (int i = tid; i < 32 * 96; i += 256) {
        int nl = i / 96, col = i % 96;
        int n = n0 + nl;
        if (n < N) xt[(size_t)n * 96 + col] = __float2half(s[nl][col]);
    }
}

// ---------------------------------------------------------------------------
// gather propagate over fp16 features, fp32 accumulation:
//   dst[n] = (HASPREV ? -prev[n] : 0) + SCALEI * sum_j norm_j * src[col_j]
// node row = W uint4 chunks (8 halves each). LPN lanes/node, CH chunks/lane.
template <int W, int LPN, int CH, int SCALEI, bool HASPREV>
__global__ void __launch_bounds__(256)
k_prop_h(const __half* __restrict__ prev, const __half* __restrict__ src,
         __half* __restrict__ dst, int N,
         const int2* __restrict__ bp_base, const int* __restrict__ deg)
{
    static_assert(LPN * CH == W, "bad chunking");
    int tid  = threadIdx.x;
    int node = blockIdx.x * (256 / LPN) + tid / LPN;
    int c4   = tid % LPN;
    if (node >= N) return;

    int d    = min(deg[node], CAP);
    int dpad = (d + 1) & ~1;
    const int2* bp = bp_base + (size_t)node * CAP;
    const uint4* s4 = (const uint4*)src;

    float2 acc[CH][4];
    if (HASPREV) {
        const uint4* p4 = (const uint4*)prev + (size_t)node * W + c4;
#pragma unroll
        for (int t = 0; t < CH; t++) {
            uint4 p = p4[t * LPN];
#pragma unroll
            for (int q = 0; q < 4; q++) {
                float2 v = __half22float2(((const __half2*)&p)[q]);
                acc[t][q] = make_float2(-v.x, -v.y);
            }
        }
    } else {
#pragma unroll
        for (int t = 0; t < CH; t++)
#pragma unroll
            for (int q = 0; q < 4; q++) acc[t][q] = make_float2(0.f, 0.f);
    }

    int2 m0 = bp[0], m1 = bp[1];          // row has CAP entries: safe
    for (int j = 0; j < dpad; j += 2) {
        int2 n0 = bp[j + 2];               // prefetch next pair (array slack)
        int2 n1 = bp[j + 3];
        const uint4* sa = s4 + (size_t)m0.x * W + c4;
        const uint4* sb = s4 + (size_t)m1.x * W + c4;
        uint4 va[CH], vb[CH];
#pragma unroll
        for (int t = 0; t < CH; t++) va[t] = sa[t * LPN];
#pragma unroll
        for (int t = 0; t < CH; t++) vb[t] = sb[t * LPN];
        float f0 = __int_as_float(m0.y) * (float)SCALEI;
        float f1 = __int_as_float(m1.y) * (float)SCALEI;
#pragma unroll
        for (int t = 0; t < CH; t++) {
#pragma unroll
            for (int q = 0; q < 4; q++) {
                float2 a = __half22float2(((const __half2*)&va[t])[q]);
                float2 b = __half22float2(((const __half2*)&vb[t])[q]);
                acc[t][q].x += f0 * a.x + f1 * b.x;
                acc[t][q].y += f0 * a.y + f1 * b.y;
            }
        }
        m0 = n0; m1 = n1;
    }

    uint4* d4 = (uint4*)dst + (size_t)node * W + c4;
#pragma unroll
    for (int t = 0; t < CH; t++) {
        uint4 o;
#pragma unroll
        for (int q = 0; q < 4; q++)
            ((__half2*)&o)[q] = __floats2half2_rn(acc[t][q].x, acc[t][q].y);
        d4[t * LPN] = o;
    }
}

// ---------------------------------------------------------------------------
// fused: for each pooled output row r:
//   out[r] = sum_{j=0..2} pval * relu( bias + sum_k T_k[col_j] @ w_k )
struct TPtrs { const __half* T[KORD]; };

template <int FIN, int FOUT>
__global__ void k_pool_cheb(TPtrs tp, const float* __restrict__ w,
                            const float* __restrict__ bias,
                            const int* __restrict__ pcols,
                            const float* __restrict__ pvals,
                            __half* __restrict__ out, int n_out)
{
    constexpr int FINP = (FIN % 2 == 0) ? FIN + 1 : FIN;   // bank-conflict pad
    constexpr int NO   = FOUT / 4;                          // outputs per thread

    __shared__ __align__(16) float sW[KORD * FIN * FOUT];
    __shared__ float sT[KORD][32 * FINP];

    int tid = threadIdx.x;
    for (int i = tid; i < KORD * FIN * FOUT; i += 128) sW[i] = w[i];

    int b  = tid & 31;
    int og = tid >> 5;      // 0..3

    float bz[NO], acc[NO];
#pragma unroll
    for (int j = 0; j < NO; j++) { bz[j] = bias[og * NO + j]; acc[j] = 0.f; }

    int r = blockIdx.x;
    if (r >= n_out) return;

#pragma unroll
    for (int j3 = 0; j3 < 3; j3++) {
        int   col = pcols[r * 3 + j3];
        float pv  = pvals[r * 3 + j3];
        __syncthreads();
#pragma unroll
        for (int k = 0; k < KORD; k++) {
            const __half* src = tp.T[k] + (size_t)col * (32 * FIN);
            for (int i = tid; i < 32 * FIN; i += 128) {
                int bb = i / FIN, ii = i - bb * FIN;
                sT[k][bb * FINP + ii] = __half2float(src[i]);
            }
        }
        __syncthreads();

        float y[NO];
#pragma unroll
        for (int j = 0; j < NO; j++) y[j] = bz[j];

#pragma unroll
        for (int k = 0; k < KORD; k++) {
            float rT[FIN];
#pragma unroll
            for (int i = 0; i < FIN; i++) rT[i] = sT[k][b * FINP + i];
#pragma unroll
            for (int i = 0; i < FIN; i++) {
                const float* wrow = &sW[(k * FIN + i) * FOUT + og * NO];
#pragma unroll
                for (int j = 0; j < NO; j += 4) {
                    float4 w4 = *(const float4*)(wrow + j);
                    y[j + 0] += rT[i] * w4.x;
                    y[j + 1] += rT[i] * w4.y;
                    y[j + 2] += rT[i] * w4.z;
                    y[j + 3] += rT[i] * w4.w;
                }
            }
        }
#pragma unroll
        for (int j = 0; j < NO; j++) acc[j] += pv * fmaxf(y[j], 0.f);
    }

    __half* o = out + ((size_t)r * 32 + b) * FOUT + og * NO;
#pragma unroll
    for (int j = 0; j < NO; j++) o[j] = __float2half(acc[j]);
}

// ---------------------------------------------------------------------------
// encoder split-K GEMM: enc[b,z] += sum_{n,f} h[n,b,f] * wenc[(n*32+f)*128+z]
__global__ void k_enc(const __half* __restrict__ h, const float* __restrict__ wenc,
                      float* __restrict__ enc, int N)
{
    __shared__ float sH[8 * 32 * 32];
    int tid = threadIdx.x;
    int n0  = blockIdx.x * 8;
    int nn  = min(8, N - n0);
    for (int i = tid; i < nn * 1024; i += 256)
        sH[i] = __half2float(h[(size_t)n0 * 1024 + i]);
    __syncthreads();

    int z  = tid & 127;
    int bh = tid >> 7;   // 0..1
    float acc[16];
#pragma unroll
    for (int j = 0; j < 16; j++) acc[j] = 0.f;

    for (int n = 0; n < nn; n++) {
#pragma unroll
        for (int f = 0; f < 32; f++) {
            float wv = wenc[((size_t)(n0 + n) * 32 + f) * 128 + z];
#pragma unroll
            for (int j = 0; j < 16; j++)
                acc[j] += wv * sH[n * 1024 + (bh * 16 + j) * 32 + f];
        }
    }
#pragma unroll
    for (int j = 0; j < 16; j++)
        atomicAdd(&enc[(bh * 16 + j) * 128 + z], acc[j]);
}

__global__ void k_final(const float* __restrict__ enc, const float* __restrict__ benc,
                        const float* __restrict__ wcls, const float* __restrict__ bcls,
                        float* __restrict__ out)
{
    int t = threadIdx.x;
    if (t >= 64) return;
    int b = t >> 1, c = t & 1;
    float a = bcls[c];
    for (int z = 0; z < 128; z++) {
        float e = fmaxf(enc[b * 128 + z] + benc[z], 0.f);
        a += e * wcls[z * 2 + c];
    }
    out[b * 2 + c] = a;
}

// ---------------------------------------------------------------------------
template <int FIN, int LPN, int CH>
static void run_cheb_h(__half* Ts[6], int N, const int2* bp, const int* deg)
{
    constexpr int W   = (32 * FIN) / 8;   // uint4 chunks per node
    static_assert(LPN * CH == W, "bad chunking");
    constexpr int NPB = 256 / LPN;
    int gN = (N + NPB - 1) / NPB;

    k_prop_h<W, LPN, CH, 1, false><<<gN, 256>>>(nullptr, Ts[0], Ts[1], N, bp, deg);
    for (int k = 2; k < KORD; k++)
        k_prop_h<W, LPN, CH, 2, true><<<gN, 256>>>(Ts[k - 2], Ts[k - 1], Ts[k], N, bp, deg);
}

extern "C" void kernel_launch(void* const* d_in, const int* in_sizes, int n_in,
                              void* d_out, int out_size)
{
    const float* x;
    const int*   edge[3];
    const float* norm[3];
    const int*   pidx[3];
    const float* pval[3];
    const float *w[3], *bb[3], *wenc, *benc, *wcls, *bcls;

    if (in_sizes[3] == 150000) {
        // reference-signature order
        x = (const float*)d_in[0];
        edge[0] = (const int*)d_in[1];  norm[0] = (const float*)d_in[2];
        edge[1] = (const int*)d_in[3];  norm[1] = (const float*)d_in[4];
        edge[2] = (const int*)d_in[5];  norm[2] = (const float*)d_in[6];
        pidx[0] = (const int*)d_in[7];  pval[0] = (const float*)d_in[8];
        pidx[1] = (const int*)d_in[9];  pval[1] = (const float*)d_in[10];
        pidx[2] = (const int*)d_in[11]; pval[2] = (const float*)d_in[12];
    } else {
        // setup_inputs dict order
        x = (const float*)d_in[0];
        edge[0] = (const int*)d_in[1];  norm[0] = (const float*)d_in[2];
        pidx[0] = (const int*)d_in[3];  pval[0] = (const float*)d_in[4];
        edge[1] = (const int*)d_in[5];  norm[1] = (const float*)d_in[6];
        pidx[1] = (const int*)d_in[7];  pval[1] = (const float*)d_in[8];
        edge[2] = (const int*)d_in[9];  norm[2] = (const float*)d_in[10];
        pidx[2] = (const int*)d_in[11]; pval[2] = (const float*)d_in[12];
    }
    w[0]  = (const float*)d_in[13]; bb[0] = (const float*)d_in[14];
    w[1]  = (const float*)d_in[15]; bb[1] = (const float*)d_in[16];
    w[2]  = (const float*)d_in[17]; bb[2] = (const float*)d_in[18];
    wenc  = (const float*)d_in[19]; benc  = (const float*)d_in[20];
    wcls  = (const float*)d_in[21]; bcls  = (const float*)d_in[22];

    __half* base = nullptr;
    cudaGetSymbolAddress((void**)&base, g_h);
    float* enc = nullptr;
    cudaGetSymbolAddress((void**)&enc, g_enc);
    int2* bpair = nullptr;
    cudaGetSymbolAddress((void**)&bpair, g_bpair);
    int* deg = nullptr;
    cudaGetSymbolAddress((void**)&deg, g_deg);

    __half* H0 = base;
    __half* H1 = base + (size_t)SLOTH;
    __half* T1 = base + (size_t)2 * SLOTH;
    __half* T2 = base + (size_t)3 * SLOTH;
    __half* T3 = base + (size_t)4 * SLOTH;
    __half* T4 = base + (size_t)5 * SLOTH;
    __half* T5 = base + (size_t)6 * SLOTH;

    // ---- setup ----
    k_init<<<(NDEG + 255) / 256, 256>>>();
    k_bucket_all<<<(E0 + E1 + E2 + 255) / 256, 256>>>(edge[0], norm[0],
                                                      edge[1], norm[1],
                                                      edge[2], norm[2]);
    k_pad<<<(N0 + 255) / 256, 256>>>();
    k_transpose_h<<<(N0 + 31) / 32, 256>>>(x, H0, N0);

    // ---- layer 0: N0, Fin=3 (12 chunks), Fout=16 ----
    {
        __half* Ts[6] = {H0, T1, T2, T3, T4, T5};
        run_cheb_h<3, 4, 3>(Ts, N0, bpair + B_OFF0, deg + DEG_OFF0);
        TPtrs tp; tp.T[0] = H0; tp.T[1] = T1; tp.T[2] = T2; tp.T[3] = T3; tp.T[4] = T4; tp.T[5] = T5;
        k_pool_cheb<3, 16><<<N1, 128>>>(tp, w[0], bb[0],
                                        pidx[0] + (size_t)N1 * 3, pval[0], H1, N1);
    }
    // ---- layer 1: N1, Fin=16 (64 chunks), Fout=16 ----
    {
        __half* Ts[6] = {H1, T1, T2, T3, T4, T5};
        run_cheb_h<16, 32, 2>(Ts, N1, bpair + B_OFF1, deg + DEG_OFF1);
        TPtrs tp; tp.T[0] = H1; tp.T[1] = T1; tp.T[2] = T2; tp.T[3] = T3; tp.T[4] = T4; tp.T[5] = T5;
        k_pool_cheb<16, 16><<<N2, 128>>>(tp, w[1], bb[1],
                                         pidx[1] + (size_t)N2 * 3, pval[1], H0, N2);
    }
    // ---- layer 2: N2, Fin=16, Fout=32 ----
    {
        __half* Ts[6] = {H0, T1, T2, T3, T4, T5};
        run_cheb_h<16, 32, 2>(Ts, N2, bpair + B_OFF2, deg + DEG_OFF2);
        TPtrs tp; tp.T[0] = H0; tp.T[1] = T1; tp.T[2] = T2; tp.T[3] = T3; tp.T[4] = T4; tp.T[5] = T5;
        k_pool_cheb<16, 32><<<N3, 128>>>(tp, w[2], bb[2],
                                         pidx[2] + (size_t)N3 * 3, pval[2], H1, N3);
    }
    // ---- encoder + classifier ----
    k_enc<<<(N3 + 7) / 8, 256>>>(H1, wenc, enc, N3);
    k_final<<<1, 64>>>(enc, benc, wcls, bcls, (float*)d_out);
}

// round 8
// speedup vs baseline: 1.1973x; 1.0100x over previous
#include <cuda_runtime.h>
#include <cuda_fp16.h>
#include <cstdint>

// ---------------------------------------------------------------------------
// CoMA forward: 3x (ChebConv K=6 -> ReLU -> Pool) -> Linear(25024,128) -> ReLU
//               -> Linear(128,2)
// Node-major fp16 feature buffers, fp32 accumulation. Each layer's 5 Chebyshev
// propagate steps run in ONE persistent kernel (grid barrier between steps),
// with bucket metadata cached in shared memory across steps.
// ---------------------------------------------------------------------------

#define BATCH 32
#define KORD 6
#define CAP 32    // bucket capacity (Poisson(6): P(>=32) ~ 1e-15)
#define SCAP 16   // smem-cached meta entries per node (deg>16 falls back to L2)
#define PGRID 592 // persistent grid: 148 SMs x 4 blocks (guaranteed resident)

#define N0 50000
#define N1 12500
#define N2 3125
#define N3 782
#define E0 300000
#define E1 75000
#define E2 18750

#define DEG_OFF0 0
#define DEG_OFF1 N0
#define DEG_OFF2 (N0 + N1)
#define NDEG (N0 + N1 + N2)

#define B_OFF0 ((size_t)0)
#define B_OFF1 ((size_t)N0 * CAP)
#define B_OFF2 ((size_t)(N0 + N1) * CAP)

// scratch: 7 slots of 6.5M halves
#define SLOTH 6500000
__device__ __align__(16) __half g_h[(size_t)7 * SLOTH + 64];
__device__ float g_enc[4096];
__device__ __align__(16) int2 g_bpair[(size_t)NDEG * CAP + 8];
__device__ int g_deg[NDEG];
__device__ int g_bar[3][16];   // per-layer barrier counters/flags

struct HP6 { __half* p[6]; };

// ---------------------------------------------------------------------------
// init: zero deg counters, enc accumulator, barriers
__global__ void k_init()
{
    int i = blockIdx.x * blockDim.x + threadIdx.x;
    if (i < NDEG) g_deg[i] = 0;
    if (i < 4096) g_enc[i] = 0.f;
    if (i < 48) ((int*)g_bar)[i] = 0;
}

// build fixed-stride incoming-edge buckets for ALL layers in one launch
__global__ void k_bucket_all(const int* __restrict__ e0, const float* __restrict__ nm0,
                             const int* __restrict__ e1, const float* __restrict__ nm1,
                             const int* __restrict__ e2, const float* __restrict__ nm2)
{
    int e = blockIdx.x * blockDim.x + threadIdx.x;
    const int* rows; const float* nm; int idx, E; int doff; size_t boff;
    if (e < E0)            { idx = e;             rows = e0; nm = nm0; E = E0; doff = DEG_OFF0; boff = B_OFF0; }
    else if (e < E0 + E1)  { idx = e - E0;        rows = e1; nm = nm1; E = E1; doff = DEG_OFF1; boff = B_OFF1; }
    else if (e < E0+E1+E2) { idx = e - E0 - E1;   rows = e2; nm = nm2; E = E2; doff = DEG_OFF2; boff = B_OFF2; }
    else return;
    int r = rows[idx];
    int c = rows[idx + E];          // cols stored after rows
    int d = atomicAdd(&g_deg[doff + r], 1);
    if (d < CAP)
        g_bpair[boff + (size_t)r * CAP + d] = make_int2(c, __float_as_int(nm[idx]));
}

// pad each bucket row to even length with (col=0, val=0)
__global__ void k_pad()
{
    int n = blockIdx.x * blockDim.x + threadIdx.x;
    if (n < N0) {
        int d = min(g_deg[DEG_OFF0 + n], CAP);
        if (d & 1) g_bpair[B_OFF0 + (size_t)n * CAP + d] = make_int2(0, 0);
    }
    if (n < N1) {
        int d = min(g_deg[DEG_OFF1 + n], CAP);
        if (d & 1) g_bpair[B_OFF1 + (size_t)n * CAP + d] = make_int2(0, 0);
    }
    if (n < N2) {
        int d = min(g_deg[DEG_OFF2 + n], CAP);
        if (d & 1) g_bpair[B_OFF2 + (size_t)n * CAP + d] = make_int2(0, 0);
    }
}

// ---------------------------------------------------------------------------
// transpose x (B, N, 3) fp32 -> xt (N, B*3) fp16, smem-tiled, uint4 stores
__global__ void k_transpose_h(const float* __restrict__ x, __half* __restrict__ xt, int N)
{
    __shared__ float s[32][100];
    int n0  = blockIdx.x * 32;
    int tid = threadIdx.x;
    for (int i = tid; i < 32 * 96; i += 256) {
        int b = i / 96, r = i % 96;        // r = nl*3 + c
        int nl = r / 3, c = r % 3;
        int n = n0 + nl;
        if (n < N) s[nl][b * 3 + c] = x[((size_t)b * N + n) * 3 + c];
    }
    __syncthreads();
    uint4* out4 = (uint4*)xt;
    for (int i = tid; i < 32 * 12; i += 256) {   // 12 uint4 per node row
        int nl = i / 12, v = i % 12;
        int n = n0 + nl;
        if (n >= N) continue;
        const float* sp = &s[nl][v * 8];
        uint4 o;
        ((__half2*)&o)[0] = __floats2half2_rn(sp[0], sp[1]);
        ((__half2*)&o)[1] = __floats2half2_rn(sp[2], sp[3]);
        ((__half2*)&o)[2] = __floats2half2_rn(sp[4], sp[5]);
        ((__half2*)&o)[3] = __floats2half2_rn(sp[6], sp[7]);
        out4[(size_t)n * 12 + v] = o;
    }
}

// ---------------------------------------------------------------------------
// gather a pair of edges into acc
template <int CH, int LPN>
__device__ __forceinline__ void gather2(float2 (&acc)[CH][4], const uint4* s4,
                                        int2 m0, int2 m1, float scale, int c4)
{
    constexpr int W = CH * LPN;
    const uint4* sa = s4 + (size_t)m0.x * W + c4;
    const uint4* sb = s4 + (size_t)m1.x * W + c4;
    uint4 va[CH], vb[CH];
#pragma unroll
    for (int t = 0; t < CH; t++) va[t] = sa[t * LPN];
#pragma unroll
    for (int t = 0; t < CH; t++) vb[t] = sb[t * LPN];
    float f0 = __int_as_float(m0.y) * scale;
    float f1 = __int_as_float(m1.y) * scale;
#pragma unroll
    for (int t = 0; t < CH; t++) {
#pragma unroll
        for (int q = 0; q < 4; q++) {
            float2 a = __half22float2(((const __half2*)&va[t])[q]);
            float2 b = __half22float2(((const __half2*)&vb[t])[q]);
            acc[t][q].x += f0 * a.x + f1 * b.x;
            acc[t][q].y += f0 * a.y + f1 * b.y;
        }
    }
}

// ---------------------------------------------------------------------------
// persistent per-layer Chebyshev kernel: runs all 5 propagate steps with a
// grid barrier between steps; bucket meta cached in smem across steps.
template <int LPN, int CH, int NPB, int PASSES>
__global__ void __launch_bounds__(256, 4)
k_cheb_layer(HP6 T, int N, const int2* __restrict__ bp_base,
             const int* __restrict__ deg, int* bar)
{
    constexpr int W = LPN * CH;
    __shared__ int2 smeta[NPB][SCAP];
    __shared__ int  sdeg[NPB];

    int tid = threadIdx.x;
    int nb  = blockIdx.x * NPB;
    int nn  = N - nb;
    if (nn > NPB) nn = NPB;
    if (nn < 0) nn = 0;

    for (int i = tid; i < nn; i += 256)
        sdeg[i] = min(deg[nb + i], CAP);
    for (int i = tid; i < nn * SCAP; i += 256) {
        int ln = i >> 4, j = i & (SCAP - 1);
        smeta[ln][j] = bp_base[(size_t)(nb + ln) * CAP + j];
    }
    __syncthreads();

    for (int k = 1; k < KORD; k++) {
        const __half* src   = T.p[k - 1];
        const __half* prevp = (k >= 2) ? T.p[k - 2] : nullptr;
        __half*       dst   = T.p[k];
        float scale = (k == 1) ? 1.f : 2.f;
        const uint4* s4 = (const uint4*)src;

#pragma unroll
        for (int p = 0; p < PASSES; p++) {
            int ln = p * (256 / LPN) + tid / LPN;
            int c4 = tid % LPN;
            if (ln < nn) {
                int node = nb + ln;
                int d    = sdeg[ln];
                int dpad = (d + 1) & ~1;

                float2 acc[CH][4];
                if (prevp) {
                    const uint4* p4 = (const uint4*)prevp + (size_t)node * W + c4;
#pragma unroll
                    for (int t = 0; t < CH; t++) {
                        uint4 pv = p4[t * LPN];
#pragma unroll
                        for (int q = 0; q < 4; q++) {
                            float2 v = __half22float2(((const __half2*)&pv)[q]);
                            acc[t][q] = make_float2(-v.x, -v.y);
                        }
                    }
                } else {
#pragma unroll
                    for (int t = 0; t < CH; t++)
#pragma unroll
                        for (int q = 0; q < 4; q++) acc[t][q] = make_float2(0.f, 0.f);
                }

                int js = dpad < SCAP ? dpad : SCAP;
                for (int j = 0; j < js; j += 2)
                    gather2<CH, LPN>(acc, s4, smeta[ln][j], smeta[ln][j + 1], scale, c4);
                for (int j = SCAP; j < dpad; j += 2)
                    gather2<CH, LPN>(acc, s4, bp_base[(size_t)node * CAP + j],
                                     bp_base[(size_t)node * CAP + j + 1], scale, c4);

                uint4* d4 = (uint4*)dst + (size_t)node * W + c4;
#pragma unroll
                for (int t = 0; t < CH; t++) {
                    uint4 o;
#pragma unroll
                    for (int q = 0; q < 4; q++)
                        ((__half2*)&o)[q] = __floats2half2_rn(acc[t][q].x, acc[t][q].y);
                    d4[t * LPN] = o;
                }
            }
        }

        if (k < KORD - 1) {
            // grid-wide barrier #k
            __threadfence();
            __syncthreads();
            if (tid == 0) {
                int t = atomicAdd(&bar[2 * k], 1);
                if (t == (int)gridDim.x - 1) {
                    atomicExch(&bar[2 * k + 1], 1);
                } else {
                    while (*(volatile int*)&bar[2 * k + 1] == 0) __nanosleep(128);
                }
                __threadfence();
            }
            __syncthreads();
        }
    }
}

// ---------------------------------------------------------------------------
// fused: for each pooled output row r:
//   out[r] = sum_{j=0..2} pval * relu( bias + sum_k T_k[col_j] @ w_k )
struct TPtrs { const __half* T[KORD]; };

template <int FIN, int FOUT>
__global__ void k_pool_cheb(TPtrs tp, const float* __restrict__ w,
                            const float* __restrict__ bias,
                            const int* __restrict__ pcols,
                            const float* __restrict__ pvals,
                            __half* __restrict__ out, int n_out)
{
    constexpr int FINP = (FIN % 2 == 0) ? FIN + 1 : FIN;   // bank-conflict pad
    constexpr int NO   = FOUT / 4;                          // outputs per thread

    __shared__ __align__(16) float sW[KORD * FIN * FOUT];
    __shared__ float sT[KORD][32 * FINP];

    int tid = threadIdx.x;
    for (int i = tid; i < KORD * FIN * FOUT; i += 128) sW[i] = w[i];

    int b  = tid & 31;
    int og = tid >> 5;      // 0..3

    float bz[NO], acc[NO];
#pragma unroll
    for (int j = 0; j < NO; j++) { bz[j] = bias[og * NO + j]; acc[j] = 0.f; }

    int r = blockIdx.x;
    if (r >= n_out) return;

#pragma unroll
    for (int j3 = 0; j3 < 3; j3++) {
        int   col = pcols[r * 3 + j3];
        float pv  = pvals[r * 3 + j3];
        __syncthreads();
#pragma unroll
        for (int k = 0; k < KORD; k++) {
            const __half* src = tp.T[k] + (size_t)col * (32 * FIN);
            for (int i = tid; i < 32 * FIN; i += 128) {
                int bb = i / FIN, ii = i - bb * FIN;
                sT[k][bb * FINP + ii] = __half2float(src[i]);
            }
        }
        __syncthreads();

        float y[NO];
#pragma unroll
        for (int j = 0; j < NO; j++) y[j] = bz[j];

#pragma unroll
        for (int k = 0; k < KORD; k++) {
            float rT[FIN];
#pragma unroll
            for (int i = 0; i < FIN; i++) rT[i] = sT[k][b * FINP + i];
#pragma unroll
            for (int i = 0; i < FIN; i++) {
                const float* wrow = &sW[(k * FIN + i) * FOUT + og * NO];
#pragma unroll
                for (int j = 0; j < NO; j += 4) {
                    float4 w4 = *(const float4*)(wrow + j);
                    y[j + 0] += rT[i] * w4.x;
                    y[j + 1] += rT[i] * w4.y;
                    y[j + 2] += rT[i] * w4.z;
                    y[j + 3] += rT[i] * w4.w;
                }
            }
        }
#pragma unroll
        for (int j = 0; j < NO; j++) acc[j] += pv * fmaxf(y[j], 0.f);
    }

    __half* o = out + ((size_t)r * 32 + b) * FOUT + og * NO;
#pragma unroll
    for (int j = 0; j < NO; j++) o[j] = __float2half(acc[j]);
}

// ---------------------------------------------------------------------------
// encoder split-K GEMM: enc[b,z] += sum_{n,f} h[n,b,f] * wenc[(n*32+f)*128+z]
__global__ void k_enc(const __half* __restrict__ h, const float* __restrict__ wenc,
                      float* __restrict__ enc, int N)
{
    __shared__ float sH[8 * 32 * 32];
    int tid = threadIdx.x;
    int n0  = blockIdx.x * 8;
    int nn  = min(8, N - n0);
    for (int i = tid; i < nn * 1024; i += 256)
        sH[i] = __half2float(h[(size_t)n0 * 1024 + i]);
    __syncthreads();

    int z  = tid & 127;
    int bh = tid >> 7;   // 0..1
    float acc[16];
#pragma unroll
    for (int j = 0; j < 16; j++) acc[j] = 0.f;

    for (int n = 0; n < nn; n++) {
#pragma unroll
        for (int f = 0; f < 32; f++) {
            float wv = wenc[((size_t)(n0 + n) * 32 + f) * 128 + z];
#pragma unroll
            for (int j = 0; j < 16; j++)
                acc[j] += wv * sH[n * 1024 + (bh * 16 + j) * 32 + f];
        }
    }
#pragma unroll
    for (int j = 0; j < 16; j++)
        atomicAdd(&enc[(bh * 16 + j) * 128 + z], acc[j]);
}

__global__ void k_final(const float* __restrict__ enc, const float* __restrict__ benc,
                        const float* __restrict__ wcls, const float* __restrict__ bcls,
                        float* __restrict__ out)
{
    int t = threadIdx.x;
    if (t >= 64) return;
    int b = t >> 1, c = t & 1;
    float a = bcls[c];
    for (int z = 0; z < 128; z++) {
        float e = fmaxf(enc[b * 128 + z] + benc[z], 0.f);
        a += e * wcls[z * 2 + c];
    }
    out[b * 2 + c] = a;
}

// ---------------------------------------------------------------------------
extern "C" void kernel_launch(void* const* d_in, const int* in_sizes, int n_in,
                              void* d_out, int out_size)
{
    const float* x;
    const int*   edge[3];
    const float* norm[3];
    const int*   pidx[3];
    const float* pval[3];
    const float *w[3], *bb[3], *wenc, *benc, *wcls, *bcls;

    if (in_sizes[3] == 150000) {
        // reference-signature order
        x = (const float*)d_in[0];
        edge[0] = (const int*)d_in[1];  norm[0] = (const float*)d_in[2];
        edge[1] = (const int*)d_in[3];  norm[1] = (const float*)d_in[4];
        edge[2] = (const int*)d_in[5];  norm[2] = (const float*)d_in[6];
        pidx[0] = (const int*)d_in[7];  pval[0] = (const float*)d_in[8];
        pidx[1] = (const int*)d_in[9];  pval[1] = (const float*)d_in[10];
        pidx[2] = (const int*)d_in[11]; pval[2] = (const float*)d_in[12];
    } else {
        // setup_inputs dict order
        x = (const float*)d_in[0];
        edge[0] = (const int*)d_in[1];  norm[0] = (const float*)d_in[2];
        pidx[0] = (const int*)d_in[3];  pval[0] = (const float*)d_in[4];
        edge[1] = (const int*)d_in[5];  norm[1] = (const float*)d_in[6];
        pidx[1] = (const int*)d_in[7];  pval[1] = (const float*)d_in[8];
        edge[2] = (const int*)d_in[9];  norm[2] = (const float*)d_in[10];
        pidx[2] = (const int*)d_in[11]; pval[2] = (const float*)d_in[12];
    }
    w[0]  = (const float*)d_in[13]; bb[0] = (const float*)d_in[14];
    w[1]  = (const float*)d_in[15]; bb[1] = (const float*)d_in[16];
    w[2]  = (const float*)d_in[17]; bb[2] = (const float*)d_in[18];
    wenc  = (const float*)d_in[19]; benc  = (const float*)d_in[20];
    wcls  = (const float*)d_in[21]; bcls  = (const float*)d_in[22];

    __half* base = nullptr;
    cudaGetSymbolAddress((void**)&base, g_h);
    float* enc = nullptr;
    cudaGetSymbolAddress((void**)&enc, g_enc);
    int2* bpair = nullptr;
    cudaGetSymbolAddress((void**)&bpair, g_bpair);
    int* deg = nullptr;
    cudaGetSymbolAddress((void**)&deg, g_deg);
    int* bar = nullptr;
    cudaGetSymbolAddress((void**)&bar, g_bar);

    __half* H0 = base;
    __half* H1 = base + (size_t)SLOTH;
    __half* T1 = base + (size_t)2 * SLOTH;
    __half* T2 = base + (size_t)3 * SLOTH;
    __half* T3 = base + (size_t)4 * SLOTH;
    __half* T4 = base + (size_t)5 * SLOTH;
    __half* T5 = base + (size_t)6 * SLOTH;

    // ---- setup ----
    k_init<<<(NDEG + 255) / 256, 256>>>();
    k_bucket_all<<<(E0 + E1 + E2 + 255) / 256, 256>>>(edge[0], norm[0],
                                                      edge[1], norm[1],
                                                      edge[2], norm[2]);
    k_pad<<<(N0 + 255) / 256, 256>>>();
    k_transpose_h<<<(N0 + 31) / 32, 256>>>(x, H0, N0);

    // ---- layer 0: N0, Fin=3 (12 uint4/row), Fout=16 ----
    {
        HP6 T; T.p[0] = H0; T.p[1] = T1; T.p[2] = T2; T.p[3] = T3; T.p[4] = T4; T.p[5] = T5;
        k_cheb_layer<4, 3, 85, 2><<<PGRID, 256>>>(T, N0, bpair + B_OFF0,
                                                  deg + DEG_OFF0, bar + 0);
        TPtrs tp; tp.T[0] = H0; tp.T[1] = T1; tp.T[2] = T2; tp.T[3] = T3; tp.T[4] = T4; tp.T[5] = T5;
        k_pool_cheb<3, 16><<<N1, 128>>>(tp, w[0], bb[0],
                                        pidx[0] + (size_t)N1 * 3, pval[0], H1, N1);
    }
    // ---- layer 1: N1, Fin=16 (64 uint4/row), Fout=16 ----
    {
        HP6 T; T.p[0] = H1; T.p[1] = T1; T.p[2] = T2; T.p[3] = T3; T.p[4] = T4; T.p[5] = T5;
        k_cheb_layer<32, 2, 22, 3><<<PGRID, 256>>>(T, N1, bpair + B_OFF1,
                                                   deg + DEG_OFF1, bar + 16);
        TPtrs tp; tp.T[0] = H1; tp.T[1] = T1; tp.T[2] = T2; tp.T[3] = T3; tp.T[4] = T4; tp.T[5] = T5;
        k_pool_cheb<16, 16><<<N2, 128>>>(tp, w[1], bb[1],
                                         pidx[1] + (size_t)N2 * 3, pval[1], H0, N2);
    }
    // ---- layer 2: N2, Fin=16, Fout=32 ----
    {
        HP6 T; T.p[0] = H0; T.p[1] = T1; T.p[2] = T2; T.p[3] = T3; T.p[4] = T4; T.p[5] = T5;
        k_cheb_layer<32, 2, 6, 1><<<PGRID, 256>>>(T, N2, bpair + B_OFF2,
                                                  deg + DEG_OFF2, bar + 32);
        TPtrs tp; tp.T[0] = H0; tp.T[1] = T1; tp.T[2] = T2; tp.T[3] = T3; tp.T[4] = T4; tp.T[5] = T5;
        k_pool_cheb<16, 32><<<N3, 128>>>(tp, w[2], bb[2],
                                         pidx[2] + (size_t)N3 * 3, pval[2], H1, N3);
    }
    // ---- encoder + classifier ----
    k_enc<<<(N3 + 7) / 8, 256>>>(H1, wenc, enc, N3);
    k_final<<<1, 64>>>(enc, benc, wcls, bcls, (float*)d_out);
}

// round 13
// speedup vs baseline: 1.2304x; 1.0277x over previous
#include <cuda_runtime.h>
#include <cuda_fp16.h>
#include <cstdint>

// ---------------------------------------------------------------------------
// CoMA forward: 3x (ChebConv K=6 -> ReLU -> Pool) -> Linear(25024,128) -> ReLU
//               -> Linear(128,2)
// Node-major fp16 feature buffers, fp32 accumulation. Per-layer persistent
// Chebyshev kernel (grid barrier between steps). Gather loop batches 4 edges'
// loads before accumulating to maximize outstanding loads per warp.
// ---------------------------------------------------------------------------

#define BATCH 32
#define KORD 6
#define CAP 32    // bucket capacity
#define SCAP 16   // smem-cached meta entries per node

#define N0 50000
#define N1 12500
#define N2 3125
#define N3 782
#define E0 300000
#define E1 75000
#define E2 18750

#define DEG_OFF0 0
#define DEG_OFF1 N0
#define DEG_OFF2 (N0 + N1)
#define NDEG (N0 + N1 + N2)

#define B_OFF0 ((size_t)0)
#define B_OFF1 ((size_t)N0 * CAP)
#define B_OFF2 ((size_t)(N0 + N1) * CAP)

#define SLOTH 6500000
__device__ __align__(16) __half g_h[(size_t)7 * SLOTH + 64];
__device__ float g_enc[4096];
__device__ __align__(16) int2 g_bpair[(size_t)NDEG * CAP + 8];
__device__ int g_deg[NDEG];
__device__ int g_bar[3][16];

struct HP6 { __half* p[6]; };

// ---------------------------------------------------------------------------
// transpose x (B, N, 3) fp32 -> xt (N, B*3) fp16  (launched FIRST)
__global__ void k_transpose_h(const float* __restrict__ x, __half* __restrict__ xt, int N)
{
    __shared__ float s[64][100];
    int n0  = blockIdx.x * 64;
    int tid = threadIdx.x;
    for (int i = tid; i < 64 * 96; i += 512) {
        int b = i / 192, r = i % 192;      // r = nl*3 + c
        int nl = r / 3, c = r % 3;
        int n = n0 + nl;
        if (n < N) s[nl][b * 3 + c] = x[((size_t)b * N + n) * 3 + c];
    }
    __syncthreads();
    uint4* out4 = (uint4*)xt;
    for (int i = tid; i < 64 * 12; i += 512) {
        int nl = i / 12, v = i % 12;
        int n = n0 + nl;
        if (n >= N) continue;
        const float* sp = &s[nl][v * 8];
        uint4 o;
        ((__half2*)&o)[0] = __floats2half2_rn(sp[0], sp[1]);
        ((__half2*)&o)[1] = __floats2half2_rn(sp[2], sp[3]);
        ((__half2*)&o)[2] = __floats2half2_rn(sp[4], sp[5]);
        ((__half2*)&o)[3] = __floats2half2_rn(sp[6], sp[7]);
        out4[(size_t)n * 12 + v] = o;
    }
}

// init: zero deg counters, enc accumulator, barriers
__global__ void k_init()
{
    int i = blockIdx.x * blockDim.x + threadIdx.x;
    if (i < NDEG) g_deg[i] = 0;
    if (i < 4096) g_enc[i] = 0.f;
    if (i < 48) ((int*)g_bar)[i] = 0;
}

// build fixed-stride incoming-edge buckets for ALL layers in one launch
__global__ void k_bucket_all(const int* __restrict__ e0, const float* __restrict__ nm0,
                             const int* __restrict__ e1, const float* __restrict__ nm1,
                             const int* __restrict__ e2, const float* __restrict__ nm2)
{
    int e = blockIdx.x * blockDim.x + threadIdx.x;
    const int* rows; const float* nm; int idx, E; int doff; size_t boff;
    if (e < E0)            { idx = e;             rows = e0; nm = nm0; E = E0; doff = DEG_OFF0; boff = B_OFF0; }
    else if (e < E0 + E1)  { idx = e - E0;        rows = e1; nm = nm1; E = E1; doff = DEG_OFF1; boff = B_OFF1; }
    else if (e < E0+E1+E2) { idx = e - E0 - E1;   rows = e2; nm = nm2; E = E2; doff = DEG_OFF2; boff = B_OFF2; }
    else return;
    int r = rows[idx];
    int c = rows[idx + E];
    int d = atomicAdd(&g_deg[doff + r], 1);
    if (d < CAP)
        g_bpair[boff + (size_t)r * CAP + d] = make_int2(c, __float_as_int(nm[idx]));
}

// pad each bucket row to a multiple of 4 with (col=0, val=0)
__global__ void k_pad()
{
    int n = blockIdx.x * blockDim.x + threadIdx.x;
    if (n < N0) {
        int d = min(g_deg[DEG_OFF0 + n], CAP), dp = min((d + 3) & ~3, CAP);
        for (int j = d; j < dp; j++) g_bpair[B_OFF0 + (size_t)n * CAP + j] = make_int2(0, 0);
    }
    if (n < N1) {
        int d = min(g_deg[DEG_OFF1 + n], CAP), dp = min((d + 3) & ~3, CAP);
        for (int j = d; j < dp; j++) g_bpair[B_OFF1 + (size_t)n * CAP + j] = make_int2(0, 0);
    }
    if (n < N2) {
        int d = min(g_deg[DEG_OFF2 + n], CAP), dp = min((d + 3) & ~3, CAP);
        for (int j = d; j < dp; j++) g_bpair[B_OFF2 + (size_t)n * CAP + j] = make_int2(0, 0);
    }
}

// ---------------------------------------------------------------------------
// persistent per-layer Chebyshev kernel; 4-edge batched gathers.
template <int LPN, int CH, int NPB, int PASSES, int MB>
__global__ void __launch_bounds__(256, MB)
k_cheb_layer(HP6 T, int N, const int2* __restrict__ bp_base,
             const int* __restrict__ deg, int* bar)
{
    constexpr int W = LPN * CH;
    __shared__ int2 smeta[NPB][SCAP];
    __shared__ int  sdeg[NPB];

    int tid = threadIdx.x;
    int nb  = blockIdx.x * NPB;
    int nn  = N - nb;
    if (nn > NPB) nn = NPB;
    if (nn < 0) nn = 0;

    for (int i = tid; i < nn; i += 256) {
        int d = min(deg[nb + i], CAP);
        sdeg[i] = min((d + 3) & ~3, CAP);   // padded degree
    }
    for (int i = tid; i < nn * SCAP; i += 256) {
        int ln = i >> 4, j = i & (SCAP - 1);
        smeta[ln][j] = bp_base[(size_t)(nb + ln) * CAP + j];
    }
    __syncthreads();

    for (int k = 1; k < KORD; k++) {
        const __half* src   = T.p[k - 1];
        const __half* prevp = (k >= 2) ? T.p[k - 2] : nullptr;
        __half*       dst   = T.p[k];
        float scale = (k == 1) ? 1.f : 2.f;
        const uint4* s4 = (const uint4*)src;

#pragma unroll
        for (int p = 0; p < PASSES; p++) {
            int ln = p * (256 / LPN) + tid / LPN;
            int c4 = tid % LPN;
            if (ln < nn) {
                int node = nb + ln;
                int dpad = sdeg[ln];

                float2 acc[CH][4];
                if (prevp) {
                    const uint4* p4 = (const uint4*)prevp + (size_t)node * W + c4;
#pragma unroll
                    for (int t = 0; t < CH; t++) {
                        uint4 pv = p4[t * LPN];
#pragma unroll
                        for (int q = 0; q < 4; q++) {
                            float2 v = __half22float2(((const __half2*)&pv)[q]);
                            acc[t][q] = make_float2(-v.x, -v.y);
                        }
                    }
                } else {
#pragma unroll
                    for (int t = 0; t < CH; t++)
#pragma unroll
                        for (int q = 0; q < 4; q++) acc[t][q] = make_float2(0.f, 0.f);
                }

                for (int j = 0; j < dpad; j += 4) {
                    int2 m0, m1, m2, m3;
                    if (j + 4 <= SCAP) {
                        m0 = smeta[ln][j];     m1 = smeta[ln][j + 1];
                        m2 = smeta[ln][j + 2]; m3 = smeta[ln][j + 3];
                    } else {
                        const int2* gp = bp_base + (size_t)node * CAP + j;
                        m0 = gp[0]; m1 = gp[1]; m2 = gp[2]; m3 = gp[3];
                    }
                    const uint4* sa = s4 + (size_t)m0.x * W + c4;
                    const uint4* sb = s4 + (size_t)m1.x * W + c4;
                    const uint4* sc = s4 + (size_t)m2.x * W + c4;
                    const uint4* sd = s4 + (size_t)m3.x * W + c4;
                    uint4 va[CH], vb[CH], vc[CH], vd[CH];
#pragma unroll
                    for (int t = 0; t < CH; t++) va[t] = sa[t * LPN];
#pragma unroll
                    for (int t = 0; t < CH; t++) vb[t] = sb[t * LPN];
#pragma unroll
                    for (int t = 0; t < CH; t++) vc[t] = sc[t * LPN];
#pragma unroll
                    for (int t = 0; t < CH; t++) vd[t] = sd[t * LPN];
                    float f0 = __int_as_float(m0.y) * scale;
                    float f1 = __int_as_float(m1.y) * scale;
                    float f2 = __int_as_float(m2.y) * scale;
                    float f3 = __int_as_float(m3.y) * scale;
#pragma unroll
                    for (int t = 0; t < CH; t++) {
#pragma unroll
                        for (int q = 0; q < 4; q++) {
                            float2 a = __half22float2(((const __half2*)&va[t])[q]);
                            float2 b = __half22float2(((const __half2*)&vb[t])[q]);
                            float2 c = __half22float2(((const __half2*)&vc[t])[q]);
                            float2 d = __half22float2(((const __half2*)&vd[t])[q]);
                            acc[t][q].x += f0 * a.x + f1 * b.x + f2 * c.x + f3 * d.x;
                            acc[t][q].y += f0 * a.y + f1 * b.y + f2 * c.y + f3 * d.y;
                        }
                    }
                }

                uint4* d4 = (uint4*)dst + (size_t)node * W + c4;
#pragma unroll
                for (int t = 0; t < CH; t++) {
                    uint4 o;
#pragma unroll
                    for (int q = 0; q < 4; q++)
                        ((__half2*)&o)[q] = __floats2half2_rn(acc[t][q].x, acc[t][q].y);
                    d4[t * LPN] = o;
                }
            }
        }

        if (k < KORD - 1) {
            __threadfence();
            __syncthreads();
            if (tid == 0) {
                int t = atomicAdd(&bar[2 * k], 1);
                if (t == (int)gridDim.x - 1) {
                    atomicExch(&bar[2 * k + 1], 1);
                } else {
                    while (*(volatile int*)&bar[2 * k + 1] == 0) __nanosleep(64);
                }
                __threadfence();
            }
            __syncthreads();
        }
    }
}

// ---------------------------------------------------------------------------
// fused pool + ChebConv output projection + ReLU
struct TPtrs { const __half* T[KORD]; };

template <int FIN, int FOUT>
__global__ void k_pool_cheb(TPtrs tp, const float* __restrict__ w,
                            const float* __restrict__ bias,
                            const int* __restrict__ pcols,
                            const float* __restrict__ pvals,
                            __half* __restrict__ out, int n_out)
{
    constexpr int FINP = (FIN % 2 == 0) ? FIN + 1 : FIN;
    constexpr int NO   = FOUT / 4;

    __shared__ __align__(16) float sW[KORD * FIN * FOUT];
    __shared__ float sT[KORD][32 * FINP];

    int tid = threadIdx.x;
    for (int i = tid; i < KORD * FIN * FOUT; i += 128) sW[i] = w[i];

    int b  = tid & 31;
    int og = tid >> 5;

    float bz[NO], acc[NO];
#pragma unroll
    for (int j = 0; j < NO; j++) { bz[j] = bias[og * NO + j]; acc[j] = 0.f; }

    int r = blockIdx.x;
    if (r >= n_out) return;

#pragma unroll
    for (int j3 = 0; j3 < 3; j3++) {
        int   col = pcols[r * 3 + j3];
        float pv  = pvals[r * 3 + j3];
        __syncthreads();
#pragma unroll
        for (int k = 0; k < KORD; k++) {
            const __half* src = tp.T[k] + (size_t)col * (32 * FIN);
            for (int i = tid; i < 32 * FIN; i += 128) {
                int bb = i / FIN, ii = i - bb * FIN;
                sT[k][bb * FINP + ii] = __half2float(src[i]);
            }
        }
        __syncthreads();

        float y[NO];
#pragma unroll
        for (int j = 0; j < NO; j++) y[j] = bz[j];

#pragma unroll
        for (int k = 0; k < KORD; k++) {
            float rT[FIN];
#pragma unroll
            for (int i = 0; i < FIN; i++) rT[i] = sT[k][b * FINP + i];
#pragma unroll
            for (int i = 0; i < FIN; i++) {
                const float* wrow = &sW[(k * FIN + i) * FOUT + og * NO];
#pragma unroll
                for (int j = 0; j < NO; j += 4) {
                    float4 w4 = *(const float4*)(wrow + j);
                    y[j + 0] += rT[i] * w4.x;
                    y[j + 1] += rT[i] * w4.y;
                    y[j + 2] += rT[i] * w4.z;
                    y[j + 3] += rT[i] * w4.w;
                }
            }
        }
#pragma unroll
        for (int j = 0; j < NO; j++) acc[j] += pv * fmaxf(y[j], 0.f);
    }

    __half* o = out + ((size_t)r * 32 + b) * FOUT + og * NO;
#pragma unroll
    for (int j = 0; j < NO; j++) o[j] = __float2half(acc[j]);
}

// ---------------------------------------------------------------------------
// encoder split-K GEMM (4 nodes per block)
__global__ void k_enc(const __half* __restrict__ h, const float* __restrict__ wenc,
                      float* __restrict__ enc, int N)
{
    __shared__ float sH[4 * 32 * 32];
    int tid = threadIdx.x;
    int n0  = blockIdx.x * 4;
    int nn  = min(4, N - n0);
    for (int i = tid; i < nn * 1024; i += 256)
        sH[i] = __half2float(h[(size_t)n0 * 1024 + i]);
    __syncthreads();

    int z  = tid & 127;
    int bh = tid >> 7;
    float acc[16];
#pragma unroll
    for (int j = 0; j < 16; j++) acc[j] = 0.f;

    for (int n = 0; n < nn; n++) {
#pragma unroll
        for (int f = 0; f < 32; f++) {
            float wv = wenc[((size_t)(n0 + n) * 32 + f) * 128 + z];
#pragma unroll
            for (int j = 0; j < 16; j++)
                acc[j] += wv * sH[n * 1024 + (bh * 16 + j) * 32 + f];
        }
    }
#pragma unroll
    for (int j = 0; j < 16; j++)
        atomicAdd(&enc[(bh * 16 + j) * 128 + z], acc[j]);
}

__global__ void k_final(const float* __restrict__ enc, const float* __restrict__ benc,
                        const float* __restrict__ wcls, const float* __restrict__ bcls,
                        float* __restrict__ out)
{
    int t = threadIdx.x;
    if (t >= 64) return;
    int b = t >> 1, c = t & 1;
    float a = bcls[c];
    for (int z = 0; z < 128; z++) {
        float e = fmaxf(enc[b * 128 + z] + benc[z], 0.f);
        a += e * wcls[z * 2 + c];
    }
    out[b * 2 + c] = a;
}

// ---------------------------------------------------------------------------
extern "C" void kernel_launch(void* const* d_in, const int* in_sizes, int n_in,
                              void* d_out, int out_size)
{
    const float* x;
    const int*   edge[3];
    const float* norm[3];
    const int*   pidx[3];
    const float* pval[3];
    const float *w[3], *bb[3], *wenc, *benc, *wcls, *bcls;

    if (in_sizes[3] == 150000) {
        x = (const float*)d_in[0];
        edge[0] = (const int*)d_in[1];  norm[0] = (const float*)d_in[2];
        edge[1] = (const int*)d_in[3];  norm[1] = (const float*)d_in[4];
        edge[2] = (const int*)d_in[5];  norm[2] = (const float*)d_in[6];
        pidx[0] = (const int*)d_in[7];  pval[0] = (const float*)d_in[8];
        pidx[1] = (const int*)d_in[9];  pval[1] = (const float*)d_in[10];
        pidx[2] = (const int*)d_in[11]; pval[2] = (const float*)d_in[12];
    } else {
        x = (const float*)d_in[0];
        edge[0] = (const int*)d_in[1];  norm[0] = (const float*)d_in[2];
        pidx[0] = (const int*)d_in[3];  pval[0] = (const float*)d_in[4];
        edge[1] = (const int*)d_in[5];  norm[1] = (const float*)d_in[6];
        pidx[1] = (const int*)d_in[7];  pval[1] = (const float*)d_in[8];
        edge[2] = (const int*)d_in[9];  norm[2] = (const float*)d_in[10];
        pidx[2] = (const int*)d_in[11]; pval[2] = (const float*)d_in[12];
    }
    w[0]  = (const float*)d_in[13]; bb[0] = (const float*)d_in[14];
    w[1]  = (const float*)d_in[15]; bb[1] = (const float*)d_in[16];
    w[2]  = (const float*)d_in[17]; bb[2] = (const float*)d_in[18];
    wenc  = (const float*)d_in[19]; benc  = (const float*)d_in[20];
    wcls  = (const float*)d_in[21]; bcls  = (const float*)d_in[22];

    __half* base = nullptr;
    cudaGetSymbolAddress((void**)&base, g_h);
    float* enc = nullptr;
    cudaGetSymbolAddress((void**)&enc, g_enc);
    int2* bpair = nullptr;
    cudaGetSymbolAddress((void**)&bpair, g_bpair);
    int* deg = nullptr;
    cudaGetSymbolAddress((void**)&deg, g_deg);
    int* bar = nullptr;
    cudaGetSymbolAddress((void**)&bar, g_bar);

    __half* H0 = base;
    __half* H1 = base + (size_t)SLOTH;
    __half* T1 = base + (size_t)2 * SLOTH;
    __half* T2 = base + (size_t)3 * SLOTH;
    __half* T3 = base + (size_t)4 * SLOTH;
    __half* T4 = base + (size_t)5 * SLOTH;
    __half* T5 = base + (size_t)6 * SLOTH;

    // ---- setup (transpose first so ncu capture slot lands on cheb/pool) ----
    k_transpose_h<<<(N0 + 63) / 64, 512>>>(x, H0, N0);
    k_init<<<(NDEG + 255) / 256, 256>>>();
    k_bucket_all<<<(E0 + E1 + E2 + 255) / 256, 256>>>(edge[0], norm[0],
                                                      edge[1], norm[1],
                                                      edge[2], norm[2]);
    k_pad<<<(N0 + 255) / 256, 256>>>();

    // ---- layer 0: N0, Fin=3 (W=12 uint4), Fout=16 ----
    {
        HP6 T; T.p[0] = H0; T.p[1] = T1; T.p[2] = T2; T.p[3] = T3; T.p[4] = T4; T.p[5] = T5;
        k_cheb_layer<4, 3, 113, 2, 3><<<444, 256>>>(T, N0, bpair + B_OFF0,
                                                    deg + DEG_OFF0, bar + 0);
        TPtrs tp; tp.T[0] = H0; tp.T[1] = T1; tp.T[2] = T2; tp.T[3] = T3; tp.T[4] = T4; tp.T[5] = T5;
        k_pool_cheb<3, 16><<<N1, 128>>>(tp, w[0], bb[0],
                                        pidx[0] + (size_t)N1 * 3, pval[0], H1, N1);
    }
    // ---- layer 1: N1, Fin=16 (W=64 uint4), Fout=16 ----
    {
        HP6 T; T.p[0] = H1; T.p[1] = T1; T.p[2] = T2; T.p[3] = T3; T.p[4] = T4; T.p[5] = T5;
        k_cheb_layer<32, 2, 22, 3, 4><<<592, 256>>>(T, N1, bpair + B_OFF1,
                                                    deg + DEG_OFF1, bar + 16);
        TPtrs tp; tp.T[0] = H1; tp.T[1] = T1; tp.T[2] = T2; tp.T[3] = T3; tp.T[4] = T4; tp.T[5] = T5;
        k_pool_cheb<16, 16><<<N2, 128>>>(tp, w[1], bb[1],
                                         pidx[1] + (size_t)N2 * 3, pval[1], H0, N2);
    }
    // ---- layer 2: N2, Fin=16, Fout=32 ----
    {
        HP6 T; T.p[0] = H0; T.p[1] = T1; T.p[2] = T2; T.p[3] = T3; T.p[4] = T4; T.p[5] = T5;
        k_cheb_layer<32, 2, 6, 1, 4><<<592, 256>>>(T, N2, bpair + B_OFF2,
                                                   deg + DEG_OFF2, bar + 32);
        TPtrs tp; tp.T[0] = H0; tp.T[1] = T1; tp.T[2] = T2; tp.T[3] = T3; tp.T[4] = T4; tp.T[5] = T5;
        k_pool_cheb<16, 32><<<N3, 128>>>(tp, w[2], bb[2],
                                         pidx[2] + (size_t)N3 * 3, pval[2], H1, N3);
    }
    // ---- encoder + classifier ----
    k_enc<<<(N3 + 3) / 4, 256>>>(H1, wenc, enc, N3);
    k_final<<<1, 64>>>(enc, benc, wcls, bcls, (float*)d_out);
}

// round 14
// speedup vs baseline: 1.2514x; 1.0170x over previous
#include <cuda_runtime.h>
#include <cuda_fp16.h>
#include <cstdint>

// ---------------------------------------------------------------------------
// CoMA forward: 3x (ChebConv K=6 -> ReLU -> Pool) -> Linear(25024,128) -> ReLU
//               -> Linear(128,2)
// Node-major fp16 features, fp32 accumulation. Per-layer persistent Chebyshev
// kernel (grid barrier between steps). NEW: own-node T_{k-2} kept in a 2-deep
// SMEM ping-pong buffer (bit-identical fp16 values) -> no global prev reads.
// ---------------------------------------------------------------------------

#define BATCH 32
#define KORD 6
#define CAP 32

#define N0 50000
#define N1 12500
#define N2 3125
#define N3 782
#define E0 300000
#define E1 75000
#define E2 18750

#define NDEG (N0 + N1 + N2)
#define B_OFF0 ((size_t)0)
#define B_OFF1 ((size_t)N0 * CAP)
#define B_OFF2 ((size_t)(N0 + N1) * CAP)
#define DEG_OFF0 0
#define DEG_OFF1 N0
#define DEG_OFF2 (N0 + N1)

#define SLOTH 6500000
__device__ __align__(16) __half g_h[(size_t)7 * SLOTH + 64];
__device__ float g_enc[4096];
__device__ __align__(16) int2 g_bpair[(size_t)NDEG * CAP + 8];
__device__ int g_deg[NDEG];
__device__ int g_bar[3][16];

struct HP6 { __half* p[6]; };

// ---------------------------------------------------------------------------
// init: zero deg counters, enc accumulator, barriers
__global__ void k_init()
{
    int i = blockIdx.x * blockDim.x + threadIdx.x;
    if (i < NDEG) g_deg[i] = 0;
    if (i < 4096) g_enc[i] = 0.f;
    if (i < 48) ((int*)g_bar)[i] = 0;
}

// build fixed-stride incoming-edge buckets for ALL layers in one launch
__global__ void k_bucket_all(const int* __restrict__ e0, const float* __restrict__ nm0,
                             const int* __restrict__ e1, const float* __restrict__ nm1,
                             const int* __restrict__ e2, const float* __restrict__ nm2)
{
    int e = blockIdx.x * blockDim.x + threadIdx.x;
    const int* rows; const float* nm; int idx, E; int doff; size_t boff;
    if (e < E0)            { idx = e;           rows = e0; nm = nm0; E = E0; doff = DEG_OFF0; boff = B_OFF0; }
    else if (e < E0 + E1)  { idx = e - E0;      rows = e1; nm = nm1; E = E1; doff = DEG_OFF1; boff = B_OFF1; }
    else if (e < E0+E1+E2) { idx = e - E0 - E1; rows = e2; nm = nm2; E = E2; doff = DEG_OFF2; boff = B_OFF2; }
    else return;
    int r = rows[idx];
    int c = rows[idx + E];
    int d = atomicAdd(&g_deg[doff + r], 1);
    if (d < CAP)
        g_bpair[boff + (size_t)r * CAP + d] = make_int2(c, __float_as_int(nm[idx]));
}

// ---------------------------------------------------------------------------
// fused: transpose x (B,N0,3) fp32 -> (N0, 96) fp16  AND  pad buckets to 4k
#define TBLOCKS 1563   // ceil(N0/32)
__global__ void k_transpad(const float* __restrict__ x, __half* __restrict__ xt)
{
    if (blockIdx.x < TBLOCKS) {
        __shared__ float s[32][100];
        int n0  = blockIdx.x * 32;
        int tid = threadIdx.x;
        for (int i = tid; i < 32 * 96; i += 256) {
            int b = i / 96, r = i % 96;
            int nl = r / 3, c = r % 3;
            int n = n0 + nl;
            if (n < N0) s[nl][b * 3 + c] = x[((size_t)b * N0 + n) * 3 + c];
        }
        __syncthreads();
        uint4* out4 = (uint4*)xt;
        for (int i = tid; i < 32 * 12; i += 256) {
            int nl = i / 12, v = i % 12;
            int n = n0 + nl;
            if (n >= N0) continue;
            const float* sp = &s[nl][v * 8];
            uint4 o;
            ((__half2*)&o)[0] = __floats2half2_rn(sp[0], sp[1]);
            ((__half2*)&o)[1] = __floats2half2_rn(sp[2], sp[3]);
            ((__half2*)&o)[2] = __floats2half2_rn(sp[4], sp[5]);
            ((__half2*)&o)[3] = __floats2half2_rn(sp[6], sp[7]);
            out4[(size_t)n * 12 + v] = o;
        }
    } else {
        int i = (blockIdx.x - TBLOCKS) * 256 + threadIdx.x;   // flat node id
        if (i >= NDEG) return;
        int d  = min(g_deg[i], CAP);
        int dp = min((d + 3) & ~3, CAP);
        size_t row = (size_t)i * CAP;
        for (int j = d; j < dp; j++) g_bpair[row + j] = make_int2(0, 0);
    }
}

// ---------------------------------------------------------------------------
// persistent per-layer Chebyshev kernel; 4-edge batched gathers; own-node
// prev (T_{k-2}) served from a 2-deep smem ping-pong buffer.
template <int LPN, int CH, int NPB, int PASSES, int MB>
__global__ void __launch_bounds__(256, MB)
k_cheb_layer(HP6 T, int N, const int2* __restrict__ bp_base,
             const int* __restrict__ deg, int* bar)
{
    constexpr int W = LPN * CH;
    static_assert(PASSES * (256 / LPN) >= NPB, "passes");
    __shared__ uint4 sping[2][NPB * W];
    __shared__ int   sdeg[NPB];

    int tid = threadIdx.x;
    int nb  = blockIdx.x * NPB;
    int nn  = N - nb;
    if (nn > NPB) nn = NPB;
    if (nn < 0) nn = 0;

    for (int i = tid; i < nn; i += 256) {
        int d = min(deg[nb + i], CAP);
        sdeg[i] = min((d + 3) & ~3, CAP);
    }
    __syncthreads();

    for (int k = 1; k < KORD; k++) {
        const __half* src = T.p[k - 1];
        __half*       dst = T.p[k];
        float scale = (k == 1) ? 1.f : 2.f;
        const uint4* s4 = (const uint4*)src;
        uint4* sp_buf = sping[k & 1];

#pragma unroll
        for (int p = 0; p < PASSES; p++) {
            int ln = p * (256 / LPN) + tid / LPN;
            int c4 = tid % LPN;
            if (ln < nn) {
                int node = nb + ln;
                int dpad = sdeg[ln];

                float2 acc[CH][4];
                if (k == 1) {
#pragma unroll
                    for (int t = 0; t < CH; t++)
#pragma unroll
                        for (int q = 0; q < 4; q++) acc[t][q] = make_float2(0.f, 0.f);
                } else if (k == 2) {
                    const uint4* p4 = (const uint4*)T.p[0] + (size_t)node * W + c4;
#pragma unroll
                    for (int t = 0; t < CH; t++) {
                        uint4 pv = p4[t * LPN];
#pragma unroll
                        for (int q = 0; q < 4; q++) {
                            float2 v = __half22float2(((const __half2*)&pv)[q]);
                            acc[t][q] = make_float2(-v.x, -v.y);
                        }
                    }
                } else {
#pragma unroll
                    for (int t = 0; t < CH; t++) {
                        uint4 pv = sp_buf[ln * W + t * LPN + c4];
#pragma unroll
                        for (int q = 0; q < 4; q++) {
                            float2 v = __half22float2(((const __half2*)&pv)[q]);
                            acc[t][q] = make_float2(-v.x, -v.y);
                        }
                    }
                }

                const int4* mrow = (const int4*)(bp_base + (size_t)node * CAP);
                for (int j = 0; j < dpad; j += 4) {
                    int4 ma = mrow[j / 2];
                    int4 mb = mrow[j / 2 + 1];
                    const uint4* sa = s4 + (size_t)ma.x * W + c4;
                    const uint4* sb = s4 + (size_t)ma.z * W + c4;
                    const uint4* sc = s4 + (size_t)mb.x * W + c4;
                    const uint4* sd = s4 + (size_t)mb.z * W + c4;
                    uint4 va[CH], vb[CH], vc[CH], vd[CH];
#pragma unroll
                    for (int t = 0; t < CH; t++) va[t] = sa[t * LPN];
#pragma unroll
                    for (int t = 0; t < CH; t++) vb[t] = sb[t * LPN];
#pragma unroll
                    for (int t = 0; t < CH; t++) vc[t] = sc[t * LPN];
#pragma unroll
                    for (int t = 0; t < CH; t++) vd[t] = sd[t * LPN];
                    float f0 = __int_as_float(ma.y) * scale;
                    float f1 = __int_as_float(ma.w) * scale;
                    float f2 = __int_as_float(mb.y) * scale;
                    float f3 = __int_as_float(mb.w) * scale;
#pragma unroll
                    for (int t = 0; t < CH; t++) {
#pragma unroll
                        for (int q = 0; q < 4; q++) {
                            float2 a = __half22float2(((const __half2*)&va[t])[q]);
                            float2 b = __half22float2(((const __half2*)&vb[t])[q]);
                            float2 c = __half22float2(((const __half2*)&vc[t])[q]);
                            float2 d = __half22float2(((const __half2*)&vd[t])[q]);
                            acc[t][q].x += f0 * a.x + f1 * b.x + f2 * c.x + f3 * d.x;
                            acc[t][q].y += f0 * a.y + f1 * b.y + f2 * c.y + f3 * d.y;
                        }
                    }
                }

                uint4* d4 = (uint4*)dst + (size_t)node * W + c4;
#pragma unroll
                for (int t = 0; t < CH; t++) {
                    uint4 o;
#pragma unroll
                    for (int q = 0; q < 4; q++)
                        ((__half2*)&o)[q] = __floats2half2_rn(acc[t][q].x, acc[t][q].y);
                    d4[t * LPN] = o;
                    if (k <= KORD - 3)                     // future prev only
                        sp_buf[ln * W + t * LPN + c4] = o;
                }
            }
        }

        if (k < KORD - 1) {
            __threadfence();
            __syncthreads();
            if (tid == 0) {
                int t = atomicAdd(&bar[2 * k], 1);
                if (t == (int)gridDim.x - 1) {
                    atomicExch(&bar[2 * k + 1], 1);
                } else {
                    while (*(volatile int*)&bar[2 * k + 1] == 0) __nanosleep(64);
                }
                __threadfence();
            }
            __syncthreads();
        }
    }
}

// ---------------------------------------------------------------------------
// fused pool + ChebConv output projection + ReLU
struct TPtrs { const __half* T[KORD]; };

template <int FIN, int FOUT>
__global__ void k_pool_cheb(TPtrs tp, const float* __restrict__ w,
                            const float* __restrict__ bias,
                            const int* __restrict__ pcols,
                            const float* __restrict__ pvals,
                            __half* __restrict__ out, int n_out)
{
    constexpr int FINP = (FIN % 2 == 0) ? FIN + 1 : FIN;
    constexpr int NO   = FOUT / 4;

    __shared__ __align__(16) float sW[KORD * FIN * FOUT];
    __shared__ float sT[KORD][32 * FINP];

    int tid = threadIdx.x;
    for (int i = tid; i < KORD * FIN * FOUT; i += 128) sW[i] = w[i];

    int b  = tid & 31;
    int og = tid >> 5;

    float bz[NO], acc[NO];
#pragma unroll
    for (int j = 0; j < NO; j++) { bz[j] = bias[og * NO + j]; acc[j] = 0.f; }

    int r = blockIdx.x;
    if (r >= n_out) return;

#pragma unroll
    for (int j3 = 0; j3 < 3; j3++) {
        int   col = pcols[r * 3 + j3];
        float pv  = pvals[r * 3 + j3];
        __syncthreads();
#pragma unroll
        for (int k = 0; k < KORD; k++) {
            const __half* src = tp.T[k] + (size_t)col * (32 * FIN);
            for (int i = tid; i < 32 * FIN; i += 128) {
                int bb = i / FIN, ii = i - bb * FIN;
                sT[k][bb * FINP + ii] = __half2float(src[i]);
            }
        }
        __syncthreads();

        float y[NO];
#pragma unroll
        for (int j = 0; j < NO; j++) y[j] = bz[j];

#pragma unroll
        for (int k = 0; k < KORD; k++) {
            float rT[FIN];
#pragma unroll
            for (int i = 0; i < FIN; i++) rT[i] = sT[k][b * FINP + i];
#pragma unroll
            for (int i = 0; i < FIN; i++) {
                const float* wrow = &sW[(k * FIN + i) * FOUT + og * NO];
#pragma unroll
                for (int j = 0; j < NO; j += 4) {
                    float4 w4 = *(const float4*)(wrow + j);
                    y[j + 0] += rT[i] * w4.x;
                    y[j + 1] += rT[i] * w4.y;
                    y[j + 2] += rT[i] * w4.z;
                    y[j + 3] += rT[i] * w4.w;
                }
            }
        }
#pragma unroll
        for (int j = 0; j < NO; j++) acc[j] += pv * fmaxf(y[j], 0.f);
    }

    __half* o = out + ((size_t)r * 32 + b) * FOUT + og * NO;
#pragma unroll
    for (int j = 0; j < NO; j++) o[j] = __float2half(acc[j]);
}

// ---------------------------------------------------------------------------
// encoder split-K GEMM (4 nodes per block)
__global__ void k_enc(const __half* __restrict__ h, const float* __restrict__ wenc,
                      float* __restrict__ enc, int N)
{
    __shared__ float sH[4 * 32 * 32];
    int tid = threadIdx.x;
    int n0  = blockIdx.x * 4;
    int nn  = min(4, N - n0);
    for (int i = tid; i < nn * 1024; i += 256)
        sH[i] = __half2float(h[(size_t)n0 * 1024 + i]);
    __syncthreads();

    int z  = tid & 127;
    int bh = tid >> 7;
    float acc[16];
#pragma unroll
    for (int j = 0; j < 16; j++) acc[j] = 0.f;

    for (int n = 0; n < nn; n++) {
#pragma unroll
        for (int f = 0; f < 32; f++) {
            float wv = wenc[((size_t)(n0 + n) * 32 + f) * 128 + z];
#pragma unroll
            for (int j = 0; j < 16; j++)
                acc[j] += wv * sH[n * 1024 + (bh * 16 + j) * 32 + f];
        }
    }
#pragma unroll
    for (int j = 0; j < 16; j++)
        atomicAdd(&enc[(bh * 16 + j) * 128 + z], acc[j]);
}

__global__ void k_final(const float* __restrict__ enc, const float* __restrict__ benc,
                        const float* __restrict__ wcls, const float* __restrict__ bcls,
                        float* __restrict__ out)
{
    int t = threadIdx.x;
    if (t >= 64) return;
    int b = t >> 1, c = t & 1;
    float a = bcls[c];
    for (int z = 0; z < 128; z++) {
        float e = fmaxf(enc[b * 128 + z] + benc[z], 0.f);
        a += e * wcls[z * 2 + c];
    }
    out[b * 2 + c] = a;
}

// ---------------------------------------------------------------------------
extern "C" void kernel_launch(void* const* d_in, const int* in_sizes, int n_in,
                              void* d_out, int out_size)
{
    const float* x;
    const int*   edge[3];
    const float* norm[3];
    const int*   pidx[3];
    const float* pval[3];
    const float *w[3], *bb[3], *wenc, *benc, *wcls, *bcls;

    if (in_sizes[3] == 150000) {
        x = (const float*)d_in[0];
        edge[0] = (const int*)d_in[1];  norm[0] = (const float*)d_in[2];
        edge[1] = (const int*)d_in[3];  norm[1] = (const float*)d_in[4];
        edge[2] = (const int*)d_in[5];  norm[2] = (const float*)d_in[6];
        pidx[0] = (const int*)d_in[7];  pval[0] = (const float*)d_in[8];
        pidx[1] = (const int*)d_in[9];  pval[1] = (const float*)d_in[10];
        pidx[2] = (const int*)d_in[11]; pval[2] = (const float*)d_in[12];
    } else {
        x = (const float*)d_in[0];
        edge[0] = (const int*)d_in[1];  norm[0] = (const float*)d_in[2];
        pidx[0] = (const int*)d_in[3];  pval[0] = (const float*)d_in[4];
        edge[1] = (const int*)d_in[5];  norm[1] = (const float*)d_in[6];
        pidx[1] = (const int*)d_in[7];  pval[1] = (const float*)d_in[8];
        edge[2] = (const int*)d_in[9];  norm[2] = (const float*)d_in[10];
        pidx[2] = (const int*)d_in[11]; pval[2] = (const float*)d_in[12];
    }
    w[0]  = (const float*)d_in[13]; bb[0] = (const float*)d_in[14];
    w[1]  = (const float*)d_in[15]; bb[1] = (const float*)d_in[16];
    w[2]  = (const float*)d_in[17]; bb[2] = (const float*)d_in[18];
    wenc  = (const float*)d_in[19]; benc  = (const float*)d_in[20];
    wcls  = (const float*)d_in[21]; bcls  = (const float*)d_in[22];

    __half* base = nullptr;
    cudaGetSymbolAddress((void**)&base, g_h);
    float* enc = nullptr;
    cudaGetSymbolAddress((void**)&enc, g_enc);
    int2* bpair = nullptr;
    cudaGetSymbolAddress((void**)&bpair, g_bpair);
    int* deg = nullptr;
    cudaGetSymbolAddress((void**)&deg, g_deg);
    int* bar = nullptr;
    cudaGetSymbolAddress((void**)&bar, g_bar);

    __half* H0 = base;
    __half* H1 = base + (size_t)SLOTH;
    __half* T1 = base + (size_t)2 * SLOTH;
    __half* T2 = base + (size_t)3 * SLOTH;
    __half* T3 = base + (size_t)4 * SLOTH;
    __half* T4 = base + (size_t)5 * SLOTH;
    __half* T5 = base + (size_t)6 * SLOTH;

    // ---- setup: init -> buckets -> {transpose + pad} ----
    k_init<<<(NDEG + 255) / 256, 256>>>();
    k_bucket_all<<<(E0 + E1 + E2 + 255) / 256, 256>>>(edge[0], norm[0],
                                                      edge[1], norm[1],
                                                      edge[2], norm[2]);
    k_transpad<<<TBLOCKS + (NDEG + 255) / 256, 256>>>(x, H0);

    // ---- layer 0: N0, Fin=3 (W=12 uint4), Fout=16 ----
    {
        HP6 T; T.p[0] = H0; T.p[1] = T1; T.p[2] = T2; T.p[3] = T3; T.p[4] = T4; T.p[5] = T5;
        k_cheb_layer<4, 3, 113, 2, 3><<<(N0 + 112) / 113, 256>>>(T, N0, bpair + B_OFF0,
                                                                 deg + DEG_OFF0, bar + 0);
        TPtrs tp; tp.T[0] = H0; tp.T[1] = T1; tp.T[2] = T2; tp.T[3] = T3; tp.T[4] = T4; tp.T[5] = T5;
        k_pool_cheb<3, 16><<<N1, 128>>>(tp, w[0], bb[0],
                                        pidx[0] + (size_t)N1 * 3, pval[0], H1, N1);
    }
    // ---- layer 1: N1, Fin=16 (W=64 uint4), Fout=16 ----
    {
        HP6 T; T.p[0] = H1; T.p[1] = T1; T.p[2] = T2; T.p[3] = T3; T.p[4] = T4; T.p[5] = T5;
        k_cheb_layer<32, 2, 22, 3, 4><<<(N1 + 21) / 22, 256>>>(T, N1, bpair + B_OFF1,
                                                               deg + DEG_OFF1, bar + 16);
        TPtrs tp; tp.T[0] = H1; tp.T[1] = T1; tp.T[2] = T2; tp.T[3] = T3; tp.T[4] = T4; tp.T[5] = T5;
        k_pool_cheb<16, 16><<<N2, 128>>>(tp, w[1], bb[1],
                                         pidx[1] + (size_t)N2 * 3, pval[1], H0, N2);
    }
    // ---- layer 2: N2, Fin=16, Fout=32 ----
    {
        HP6 T; T.p[0] = H0; T.p[1] = T1; T.p[2] = T2; T.p[3] = T3; T.p[4] = T4; T.p[5] = T5;
        k_cheb_layer<32, 2, 6, 1, 4><<<(N2 + 5) / 6, 256>>>(T, N2, bpair + B_OFF2,
                                                            deg + DEG_OFF2, bar + 32);
        TPtrs tp; tp.T[0] = H0; tp.T[1] = T1; tp.T[2] = T2; tp.T[3] = T3; tp.T[4] = T4; tp.T[5] = T5;
        k_pool_cheb<16, 32><<<N3, 128>>>(tp, w[2], bb[2],
                                         pidx[2] + (size_t)N3 * 3, pval[2], H1, N3);
    }
    // ---- encoder + classifier ----
    k_enc<<<(N3 + 3) / 4, 256>>>(H1, wenc, enc, N3);
    k_final<<<1, 64>>>(enc, benc, wcls, bcls, (float*)d_out);
}